// round 13
// baseline (speedup 1.0000x reference)
#include <cuda_runtime.h>
#include <cuda_fp16.h>
#include <math.h>
#include <stddef.h>
#include <stdint.h>

// ---------------- problem constants ----------------
#define TOKS   8192
#define CDIM   768
#define HID    384
#define NHEAD  12
#define HDIM   64
#define SEQ    1024
#define QKVC   2304
#define NBH    96

// ---------------- scratch ---------------------------
__device__ __half g_h16[(size_t)TOKS * CDIM];
__device__ float  g_qkv[(size_t)TOKS * QKVC];
__device__ __half g_att16[(size_t)TOKS * CDIM];
__device__ float  g_x1[(size_t)TOKS * CDIM];
__device__ __half g_fc1h[(size_t)TOKS * HID];
__device__ __half g_wqkv_h[(size_t)QKVC * CDIM];
__device__ __half g_wproj_h[(size_t)CDIM * CDIM];
__device__ __half g_wfc1_h[(size_t)HID * CDIM];
__device__ __half g_wfc2_h[(size_t)CDIM * HID];

typedef unsigned long long u64;

// ---------------- helpers -----------------------
__device__ __forceinline__ uint32_t smem_u32(const void* p) {
    uint32_t a;
    asm("{ .reg .u64 t; cvta.to.shared.u64 t, %1; cvt.u32.u64 %0, t; }" : "=r"(a) : "l"(p));
    return a;
}
__device__ __forceinline__ void cp_async16(uint32_t dst, const void* src) {
    asm volatile("cp.async.cg.shared.global [%0], [%1], 16;" :: "r"(dst), "l"(src));
}
#define CP_COMMIT() asm volatile("cp.async.commit_group;" ::: "memory")

__device__ __forceinline__ void sts16(uint32_t a, unsigned short v) {
    asm volatile("st.shared.u16 [%0], %1;" :: "r"(a), "h"(v));
}
__device__ __forceinline__ void ldsm_x4(uint32_t addr, uint32_t &r0, uint32_t &r1,
                                        uint32_t &r2, uint32_t &r3) {
    asm volatile("ldmatrix.sync.aligned.m8n8.x4.shared.b16 {%0,%1,%2,%3}, [%4];"
                 : "=r"(r0), "=r"(r1), "=r"(r2), "=r"(r3) : "r"(addr));
}

__device__ __forceinline__ void mma_fp16(float* d, const uint32_t* a, const uint32_t* b) {
    asm volatile(
        "mma.sync.aligned.m16n8k16.row.col.f32.f16.f16.f32 "
        "{%0,%1,%2,%3}, {%4,%5,%6,%7}, {%8,%9}, {%0,%1,%2,%3};"
        : "+f"(d[0]), "+f"(d[1]), "+f"(d[2]), "+f"(d[3])
        : "r"(a[0]), "r"(a[1]), "r"(a[2]), "r"(a[3]), "r"(b[0]), "r"(b[1]));
}
__device__ __forceinline__ void mma_bf16(float* d, const uint32_t* a, const uint32_t* b) {
    asm volatile(
        "mma.sync.aligned.m16n8k16.row.col.f32.bf16.bf16.f32 "
        "{%0,%1,%2,%3}, {%4,%5,%6,%7}, {%8,%9}, {%0,%1,%2,%3};"
        : "+f"(d[0]), "+f"(d[1]), "+f"(d[2]), "+f"(d[3])
        : "r"(a[0]), "r"(a[1]), "r"(a[2]), "r"(a[3]), "r"(b[0]), "r"(b[1]));
}

__device__ __forceinline__ uint32_t pack_bf16x2(float lo_e, float hi_e) {
    uint32_t r;
    asm("cvt.rn.bf16x2.f32 %0, %1, %2;" : "=r"(r) : "f"(hi_e), "f"(lo_e));
    return r;
}
__device__ __forceinline__ uint32_t pack_half2(float lo_e, float hi_e) {
    uint32_t r;
    asm("cvt.rn.f16x2.f32 %0, %1, %2;" : "=r"(r) : "f"(hi_e), "f"(lo_e));
    return r;
}
__device__ __forceinline__ void split_bf16(float x, float y, uint32_t &hp, uint32_t &lp) {
    hp = pack_bf16x2(x, y);
    float hx = __uint_as_float(hp << 16);
    float hy = __uint_as_float(hp & 0xffff0000u);
    lp = pack_bf16x2(x - hx, y - hy);
}

// ---------------- weight transpose+convert: out[n][k] = fp16(in[k][n]) ----
__global__ void transpose_kernel(const float* __restrict__ in, __half* __restrict__ out,
                                 int K, int N) {
    __shared__ float t[32][33];
    int bn = blockIdx.x << 5, bk = blockIdx.y << 5;
    int tx = threadIdx.x, ty = threadIdx.y;   // 32 x 8
#pragma unroll
    for (int i = 0; i < 4; i++)
        t[ty + i * 8][tx] = in[(size_t)(bk + ty + i * 8) * N + bn + tx];
    __syncthreads();
#pragma unroll
    for (int i = 0; i < 4; i++)
        out[(size_t)(bn + ty + i * 8) * K + bk + tx] = __float2half_rn(t[tx][ty + i * 8]);
}

// ---------------- LayerNorm (fp32 in -> fp16 out) -------------------------
__global__ void ln_kernel(const float* __restrict__ x, const float* __restrict__ w,
                          const float* __restrict__ b, __half* __restrict__ out) {
    int row = blockIdx.x;
    const float* xr = x + (size_t)row * CDIM;
    __half* orow = out + (size_t)row * CDIM;
    int t = threadIdx.x;
    float v0 = xr[t], v1 = xr[t + 256], v2 = xr[t + 512];
    float s = v0 + v1 + v2;
    float q = v0 * v0 + v1 * v1 + v2 * v2;
#pragma unroll
    for (int o = 16; o; o >>= 1) {
        s += __shfl_xor_sync(0xffffffffu, s, o);
        q += __shfl_xor_sync(0xffffffffu, q, o);
    }
    __shared__ float rs[8], rq[8];
    if ((t & 31) == 0) { rs[t >> 5] = s; rq[t >> 5] = q; }
    __syncthreads();
    if (t < 32) {
        float us = (t < 8) ? rs[t] : 0.f;
        float uq = (t < 8) ? rq[t] : 0.f;
#pragma unroll
        for (int o = 4; o; o >>= 1) {
            us += __shfl_xor_sync(0xffffffffu, us, o);
            uq += __shfl_xor_sync(0xffffffffu, uq, o);
        }
        if (t == 0) { rs[0] = us; rq[0] = uq; }
    }
    __syncthreads();
    float mu  = rs[0] * (1.f / CDIM);
    float var = rq[0] * (1.f / CDIM) - mu * mu;
    float inv = rsqrtf(var + 1e-5f);
    orow[t]       = __float2half_rn((v0 - mu) * inv * w[t]       + b[t]);
    orow[t + 256] = __float2half_rn((v1 - mu) * inv * w[t + 256] + b[t + 256]);
    orow[t + 512] = __float2half_rn((v2 - mu) * inv * w[t + 512] + b[t + 512]);
}

// ---------------- fp16 GEMM with ldmatrix fragments, 2 CTAs/SM ------------
#define GSTG 16384u
__global__ void __launch_bounds__(256, 2)
gemm_fp16(const __half* __restrict__ A, const __half* __restrict__ Bt,
          float* __restrict__ C, __half* __restrict__ C16, int N, int K,
          const float* __restrict__ bias, const float* __restrict__ resid,
          int gelu_flag) {
    extern __shared__ char smem[];
    const uint32_t sb = smem_u32(smem);
    const int tid = threadIdx.x;
    const int wid = tid >> 5, lane = tid & 31;
    const int warp_m = wid & 1, warp_n = wid >> 1;
    const int cl = lane & 3;
    const int g  = lane >> 2;
    const int bn = blockIdx.x << 7, bm = blockIdx.y << 7;
    const int nBK = K >> 5;

    float d[4][4][4];
#pragma unroll
    for (int i = 0; i < 4; i++)
#pragma unroll
        for (int j = 0; j < 4; j++)
#pragma unroll
            for (int e = 0; e < 4; e++) d[i][j][e] = 0.f;

#define LOADT(k0, buf)                                                          \
    {                                                                           \
        uint32_t base = sb + ((buf) ? GSTG : 0u);                               \
        _Pragma("unroll")                                                       \
        for (int i = 0; i < 2; i++) {                                           \
            int id = tid + (i << 8);                                            \
            int row = id >> 2, kh = id & 3;                                     \
            uint32_t dst = base + (uint32_t)(row << 6)                          \
                         + (uint32_t)((kh ^ ((row >> 1) & 3)) << 4);            \
            cp_async16(dst, A + (size_t)(bm + row) * K + (k0) + (kh << 3));     \
            cp_async16(dst + 8192u,                                             \
                       Bt + (size_t)(bn + row) * K + (k0) + (kh << 3));         \
        }                                                                       \
        CP_COMMIT();                                                            \
    }

    LOADT(0, 0);
    if (nBK > 1) LOADT(32, 1);

    const int ar  = (lane & 7) + (((lane >> 3) & 1) << 3);
    const int khp = lane >> 4;
    const int rowa = warp_m * 64 + ar;
    const int rowb = warp_n * 32 + ar;
    const uint32_t swa = (uint32_t)((rowa >> 1) & 3);
    const uint32_t swb = (uint32_t)((rowb >> 1) & 3);

    for (int c = 0; c < nBK; c++) {
        int buf = c & 1;
        if (c == nBK - 1) asm volatile("cp.async.wait_group 0;" ::: "memory");
        else              asm volatile("cp.async.wait_group 1;" ::: "memory");
        __syncthreads();

        const uint32_t Sb = sb + (buf ? GSTG : 0u);
        const uint32_t Ab = Sb + (uint32_t)(rowa << 6);
        const uint32_t Bb = Sb + 8192u + (uint32_t)(rowb << 6);

#pragma unroll
        for (int ks = 0; ks < 2; ks++) {
            uint32_t kha = (uint32_t)(((2 * ks + khp) ^ swa) << 4);
            uint32_t khb = (uint32_t)(((2 * ks + khp) ^ swb) << 4);
            uint32_t av[4][4], bv[4][2];
#pragma unroll
            for (int mi = 0; mi < 4; mi++)
                ldsm_x4(Ab + (uint32_t)(mi << 10) + kha,
                        av[mi][0], av[mi][1], av[mi][2], av[mi][3]);
#pragma unroll
            for (int j2 = 0; j2 < 2; j2++)
                ldsm_x4(Bb + (uint32_t)(j2 << 10) + khb,
                        bv[j2 * 2][0], bv[j2 * 2 + 1][0],
                        bv[j2 * 2][1], bv[j2 * 2 + 1][1]);
#pragma unroll
            for (int i = 0; i < 4; i++)
#pragma unroll
                for (int j = 0; j < 4; j++) mma_fp16(d[i][j], av[i], bv[j]);
        }
        __syncthreads();
        if (c + 2 < nBK) LOADT((c + 2) << 5, buf);
    }

    const int m0w = bm + warp_m * 64 + g;
    const int n0w = bn + warp_n * 32 + cl * 2;
#pragma unroll
    for (int i = 0; i < 4; i++) {
#pragma unroll
        for (int h = 0; h < 2; h++) {
            int row = m0w + i * 16 + h * 8;
            const float* Rrow = resid ? resid + (size_t)row * N : (const float*)0;
#pragma unroll
            for (int j = 0; j < 4; j++) {
                int col = n0w + j * 8;
                float v0 = d[i][j][h * 2 + 0];
                float v1 = d[i][j][h * 2 + 1];
                if (bias) { v0 += bias[col]; v1 += bias[col + 1]; }
                if (gelu_flag) {
                    v0 = 0.5f * v0 * (1.f + erff(v0 * 0.70710678118654752f));
                    v1 = 0.5f * v1 * (1.f + erff(v1 * 0.70710678118654752f));
                }
                if (Rrow) { v0 += Rrow[col]; v1 += Rrow[col + 1]; }
                if (C16) {
                    *(uint32_t*)&C16[(size_t)row * N + col] = pack_half2(v0, v1);
                } else {
                    *(float2*)&C[(size_t)row * N + col] = make_float2(v0, v1);
                }
            }
        }
    }
#undef LOADT
}
#define GEMM_SMEM (2 * 16384)

// ---------------- flash attention (R12 body), 2 CTAs/SM -------------------
#define QS 36
#define QSB 144u

__global__ void __launch_bounds__(256, 2)
flash_mma(const float* __restrict__ qkv, __half* __restrict__ att16) {
    extern __shared__ char smc[];
    uint32_t* Qhb = (uint32_t*)smc;            // [128][QS]
    uint32_t* Qlb = Qhb + 128 * QS;            // [128][QS]
    uint32_t* Khb = Qlb + 128 * QS;            // [64][QS]
    uint32_t* Klb = Khb + 64 * QS;             // [64][QS]
    uint32_t* Vth = Klb + 64 * QS;             // [64 d][QS] fp16 kv-pairs
    uint32_t* Ph  = Vth + 64 * QS;             // [128 q][QS] fp16 kv-pairs

    const int tid = threadIdx.x;
    const int wid = tid >> 5, lane = tid & 31;
    const int r = lane >> 2, cl = lane & 3;
    const int qb = blockIdx.x << 7;
    const int bh = blockIdx.y;
    const int b = bh / NHEAD, h = bh % NHEAD;
    const float* qptr = qkv + (size_t)b * SEQ * QKVC + h * HDIM;
    const float* kptr = qptr + CDIM;
    const float* vptr = qptr + 2 * CDIM;
    const uint32_t vth_sb = smem_u32(Vth);

    {
        int row = tid >> 1;
        const float* src = qptr + (size_t)(qb + row) * QKVC;
#pragma unroll
        for (int e = 0; e < 8; e++) {
            int c4 = ((tid & 1) << 3) + e;
            float4 v = *(const float4*)(src + (c4 << 2));
            v.x *= 8.f; v.y *= 8.f; v.z *= 8.f; v.w *= 8.f;
            uint32_t h0, l0, h1, l1;
            split_bf16(v.x, v.y, h0, l0);
            split_bf16(v.z, v.w, h1, l1);
            Qhb[row * QS + 2 * c4]     = h0;
            Qhb[row * QS + 2 * c4 + 1] = h1;
            Qlb[row * QS + 2 * c4]     = l0;
            Qlb[row * QS + 2 * c4 + 1] = l1;
        }
    }

    float mi0 = -3.4e38f, mi1 = -3.4e38f, li0 = 0.f, li1 = 0.f;
    float o[8][4];
#pragma unroll
    for (int j = 0; j < 8; j++)
#pragma unroll
        for (int e = 0; e < 4; e++) o[j][e] = 0.f;

    const int m0 = wid << 4;
    const int fr8 = (lane & 7) + (((lane >> 3) & 1) << 3);
    const uint32_t khf16 = (uint32_t)(lane >> 4) << 4;
    const uint32_t qoff  = (uint32_t)(m0 + fr8) * QSB + khf16;
    const uint32_t koff0 = (uint32_t)fr8 * QSB + khf16;
    const uint32_t qh_b = smem_u32(Qhb) + qoff;
    const uint32_t ql_b = smem_u32(Qlb) + qoff;
    const uint32_t kh_b = smem_u32(Khb) + koff0;
    const uint32_t kl_b = smem_u32(Klb) + koff0;
    const uint32_t ph_b = smem_u32(Ph) + qoff;
    const uint32_t vt_b = vth_sb + koff0;

    for (int t = 0; t < 16; t++) {
        __syncthreads();
        {
            int row = tid >> 2;
            const float* ksrc = kptr + (size_t)((t << 6) + row) * QKVC;
            const float* vsrc = vptr + (size_t)((t << 6) + row) * QKVC;
            uint32_t vbase = vth_sb + (uint32_t)((row >> 1) << 2) + ((row & 1) << 1);
#pragma unroll
            for (int e = 0; e < 4; e++) {
                int c4 = (tid & 3) + (e << 2);
                float4 v = *(const float4*)(ksrc + (c4 << 2));
                uint32_t h0, l0, h1, l1;
                split_bf16(v.x, v.y, h0, l0);
                split_bf16(v.z, v.w, h1, l1);
                Khb[row * QS + 2 * c4]     = h0;
                Khb[row * QS + 2 * c4 + 1] = h1;
                Klb[row * QS + 2 * c4]     = l0;
                Klb[row * QS + 2 * c4 + 1] = l1;
                float4 vv = *(const float4*)(vsrc + (c4 << 2));
                int dc = c4 << 2;
                sts16(vbase + (uint32_t)((dc + 0) * QS << 2),
                      __half_as_ushort(__float2half_rn(vv.x)));
                sts16(vbase + (uint32_t)((dc + 1) * QS << 2),
                      __half_as_ushort(__float2half_rn(vv.y)));
                sts16(vbase + (uint32_t)((dc + 2) * QS << 2),
                      __half_as_ushort(__float2half_rn(vv.z)));
                sts16(vbase + (uint32_t)((dc + 3) * QS << 2),
                      __half_as_ushort(__float2half_rn(vv.w)));
            }
        }
        __syncthreads();

        float s[8][4];
#pragma unroll
        for (int j = 0; j < 8; j++)
#pragma unroll
            for (int e = 0; e < 4; e++) s[j][e] = 0.f;

#pragma unroll
        for (int ks = 0; ks < 4; ks++) {
            uint32_t ko = (uint32_t)(ks << 5);
            uint32_t ah[4], al[4];
            ldsm_x4(qh_b + ko, ah[0], ah[1], ah[2], ah[3]);
            ldsm_x4(ql_b + ko, al[0], al[1], al[2], al[3]);
#pragma unroll
            for (int jp = 0; jp < 4; jp++) {
                uint32_t jo = (uint32_t)(jp * 16) * QSB + ko;
                uint32_t bh2[2][2], bl2[2][2];
                ldsm_x4(kh_b + jo, bh2[0][0], bh2[1][0], bh2[0][1], bh2[1][1]);
                ldsm_x4(kl_b + jo, bl2[0][0], bl2[1][0], bl2[0][1], bl2[1][1]);
#pragma unroll
                for (int jj = 0; jj < 2; jj++) {
                    int j = jp * 2 + jj;
                    mma_bf16(s[j], ah, bh2[jj]);
                    mma_bf16(s[j], al, bh2[jj]);
                    mma_bf16(s[j], ah, bl2[jj]);
                }
            }
        }

        float mx0 = s[0][0], mx1 = s[0][2];
#pragma unroll
        for (int j = 0; j < 8; j++) {
            mx0 = fmaxf(mx0, fmaxf(s[j][0], s[j][1]));
            mx1 = fmaxf(mx1, fmaxf(s[j][2], s[j][3]));
        }
        mx0 = fmaxf(mx0, __shfl_xor_sync(0xffffffffu, mx0, 1));
        mx0 = fmaxf(mx0, __shfl_xor_sync(0xffffffffu, mx0, 2));
        mx1 = fmaxf(mx1, __shfl_xor_sync(0xffffffffu, mx1, 1));
        mx1 = fmaxf(mx1, __shfl_xor_sync(0xffffffffu, mx1, 2));
        float mn0 = fmaxf(mi0, mx0), mn1 = fmaxf(mi1, mx1);
        float sc0 = __expf(mi0 - mn0), sc1 = __expf(mi1 - mn1);
        mi0 = mn0; mi1 = mn1;
        float sum0 = 0.f, sum1 = 0.f;
#pragma unroll
        for (int j = 0; j < 8; j++) {
            s[j][0] = __expf(s[j][0] - mn0);
            s[j][1] = __expf(s[j][1] - mn0);
            s[j][2] = __expf(s[j][2] - mn1);
            s[j][3] = __expf(s[j][3] - mn1);
            sum0 += s[j][0] + s[j][1];
            sum1 += s[j][2] + s[j][3];
        }
        sum0 += __shfl_xor_sync(0xffffffffu, sum0, 1);
        sum0 += __shfl_xor_sync(0xffffffffu, sum0, 2);
        sum1 += __shfl_xor_sync(0xffffffffu, sum1, 1);
        sum1 += __shfl_xor_sync(0xffffffffu, sum1, 2);
        li0 = li0 * sc0 + sum0;
        li1 = li1 * sc1 + sum1;
#pragma unroll
        for (int j = 0; j < 8; j++) {
            o[j][0] *= sc0; o[j][1] *= sc0;
            o[j][2] *= sc1; o[j][3] *= sc1;
        }

#pragma unroll
        for (int j = 0; j < 8; j++) {
            Ph[(m0 + r) * QS + (j << 2) + cl]     = pack_half2(s[j][0], s[j][1]);
            Ph[(m0 + r + 8) * QS + (j << 2) + cl] = pack_half2(s[j][2], s[j][3]);
        }
        __syncwarp();

#pragma unroll
        for (int ks = 0; ks < 4; ks++) {
            uint32_t ko = (uint32_t)(ks << 5);
            uint32_t a[4];
            ldsm_x4(ph_b + ko, a[0], a[1], a[2], a[3]);
#pragma unroll
            for (int jp = 0; jp < 4; jp++) {
                uint32_t jo = (uint32_t)(jp * 16) * QSB + ko;
                uint32_t b2[2][2];
                ldsm_x4(vt_b + jo, b2[0][0], b2[1][0], b2[0][1], b2[1][1]);
                mma_fp16(o[jp * 2 + 0], a, b2[0]);
                mma_fp16(o[jp * 2 + 1], a, b2[1]);
            }
        }
    }

    {
        float inv0 = 1.f / li0, inv1 = 1.f / li1;
        __half* o0 = att16 + ((size_t)(b * SEQ + qb + m0 + r)) * CDIM + h * HDIM;
        __half* o1 = o0 + 8 * CDIM;
#pragma unroll
        for (int j = 0; j < 8; j++) {
            int col = (j << 3) + (cl << 1);
            *(uint32_t*)&o0[col] = pack_half2(o[j][0] * inv0, o[j][1] * inv0);
            *(uint32_t*)&o1[col] = pack_half2(o[j][2] * inv1, o[j][3] * inv1);
        }
    }
}
#define FLASH_SMEM ((128 + 128 + 64 + 64 + 64 + 128) * QS * 4)

// ---------------- launch --------------------------------------------------
extern "C" void kernel_launch(void* const* d_in, const int* in_sizes, int n_in,
                              void* d_out, int out_size) {
    const float* x     = (const float*)d_in[0];
    const float* ln1w  = (const float*)d_in[1];
    const float* ln1b  = (const float*)d_in[2];
    const float* ln2w  = (const float*)d_in[3];
    const float* ln2b  = (const float*)d_in[4];
    const float* wqkv  = (const float*)d_in[5];
    const float* wproj = (const float*)d_in[6];
    const float* wfc1  = (const float*)d_in[7];
    const float* bfc1  = (const float*)d_in[8];
    const float* wfc2  = (const float*)d_in[9];
    const float* bfc2  = (const float*)d_in[10];
    float* out = (float*)d_out;

    __half *p_h16, *p_att16, *p_fc1h, *p_wqkv_h, *p_wproj_h, *p_wfc1_h, *p_wfc2_h;
    float *p_qkv, *p_x1;
    cudaGetSymbolAddress((void**)&p_h16, g_h16);
    cudaGetSymbolAddress((void**)&p_qkv, g_qkv);
    cudaGetSymbolAddress((void**)&p_att16, g_att16);
    cudaGetSymbolAddress((void**)&p_x1, g_x1);
    cudaGetSymbolAddress((void**)&p_fc1h, g_fc1h);
    cudaGetSymbolAddress((void**)&p_wqkv_h, g_wqkv_h);
    cudaGetSymbolAddress((void**)&p_wproj_h, g_wproj_h);
    cudaGetSymbolAddress((void**)&p_wfc1_h, g_wfc1_h);
    cudaGetSymbolAddress((void**)&p_wfc2_h, g_wfc2_h);

    cudaFuncSetAttribute(flash_mma, cudaFuncAttributeMaxDynamicSharedMemorySize,
                         FLASH_SMEM);
    cudaFuncSetAttribute(gemm_fp16, cudaFuncAttributeMaxDynamicSharedMemorySize,
                         GEMM_SMEM);

    dim3 tb(32, 8);
    transpose_kernel<<<dim3(QKVC / 32, CDIM / 32), tb>>>(wqkv, p_wqkv_h, CDIM, QKVC);
    transpose_kernel<<<dim3(CDIM / 32, CDIM / 32), tb>>>(wproj, p_wproj_h, CDIM, CDIM);
    transpose_kernel<<<dim3(HID / 32, CDIM / 32), tb>>>(wfc1, p_wfc1_h, CDIM, HID);
    transpose_kernel<<<dim3(CDIM / 32, HID / 32), tb>>>(wfc2, p_wfc2_h, HID, CDIM);

    // 1) h = LN1(x)  (fp16 out)
    ln_kernel<<<TOKS, 256>>>(x, ln1w, ln1b, p_h16);
    // 2) qkv = h @ w_qkv  (fp32 out, feeds flash)
    gemm_fp16<<<dim3(QKVC / 128, TOKS / 128), 256, GEMM_SMEM>>>(
        p_h16, p_wqkv_h, p_qkv, nullptr, QKVC, CDIM, nullptr, nullptr, 0);
    // 3-5) fused attention (att out fp16)
    flash_mma<<<dim3(SEQ / 128, NBH), 256, FLASH_SMEM>>>(p_qkv, p_att16);
    // 6) x1 = x + att @ w_proj  (fp32 out)
    gemm_fp16<<<dim3(CDIM / 128, TOKS / 128), 256, GEMM_SMEM>>>(
        p_att16, p_wproj_h, p_x1, nullptr, CDIM, CDIM, nullptr, x, 0);
    // 7) h = LN2(x1)  (fp16 out)
    ln_kernel<<<TOKS, 256>>>(p_x1, ln2w, ln2b, p_h16);
    // 8) fc1 = gelu(h @ w_fc1 + b_fc1)  (fp16 out)
    gemm_fp16<<<dim3(HID / 128, TOKS / 128), 256, GEMM_SMEM>>>(
        p_h16, p_wfc1_h, nullptr, p_fc1h, HID, CDIM, bfc1, nullptr, 1);
    // 9) out = x1 + fc1 @ w_fc2 + b_fc2  (fp32 out)
    gemm_fp16<<<dim3(CDIM / 128, TOKS / 128), 256, GEMM_SMEM>>>(
        p_fc1h, p_wfc2_h, out, nullptr, CDIM, HID, bfc2, p_x1, 0);
}

// round 14
// speedup vs baseline: 1.0378x; 1.0378x over previous
#include <cuda_runtime.h>
#include <cuda_fp16.h>
#include <math.h>
#include <stddef.h>
#include <stdint.h>

// ---------------- problem constants ----------------
#define TOKS   8192
#define CDIM   768
#define HID    384
#define NHEAD  12
#define HDIM   64
#define SEQ    1024
#define QKVC   2304
#define NBH    96

// ---------------- scratch ---------------------------
__device__ __half g_h16[(size_t)TOKS * CDIM];
__device__ float  g_qkv[(size_t)TOKS * QKVC];
__device__ __half g_att16[(size_t)TOKS * CDIM];
__device__ float  g_x1[(size_t)TOKS * CDIM];
__device__ __half g_fc1h[(size_t)TOKS * HID];
__device__ __half g_wqkv_h[(size_t)QKVC * CDIM];
__device__ __half g_wproj_h[(size_t)CDIM * CDIM];
__device__ __half g_wfc1_h[(size_t)HID * CDIM];
__device__ __half g_wfc2_h[(size_t)CDIM * HID];

typedef unsigned long long u64;

// ---------------- helpers -----------------------
__device__ __forceinline__ uint32_t smem_u32(const void* p) {
    uint32_t a;
    asm("{ .reg .u64 t; cvta.to.shared.u64 t, %1; cvt.u32.u64 %0, t; }" : "=r"(a) : "l"(p));
    return a;
}
__device__ __forceinline__ void cp_async16(uint32_t dst, const void* src) {
    asm volatile("cp.async.cg.shared.global [%0], [%1], 16;" :: "r"(dst), "l"(src));
}
#define CP_COMMIT() asm volatile("cp.async.commit_group;" ::: "memory")

__device__ __forceinline__ void sts16(uint32_t a, unsigned short v) {
    asm volatile("st.shared.u16 [%0], %1;" :: "r"(a), "h"(v));
}
__device__ __forceinline__ void ldsm_x4(uint32_t addr, uint32_t &r0, uint32_t &r1,
                                        uint32_t &r2, uint32_t &r3) {
    asm volatile("ldmatrix.sync.aligned.m8n8.x4.shared.b16 {%0,%1,%2,%3}, [%4];"
                 : "=r"(r0), "=r"(r1), "=r"(r2), "=r"(r3) : "r"(addr));
}

__device__ __forceinline__ void mma_fp16(float* d, const uint32_t* a, const uint32_t* b) {
    asm volatile(
        "mma.sync.aligned.m16n8k16.row.col.f32.f16.f16.f32 "
        "{%0,%1,%2,%3}, {%4,%5,%6,%7}, {%8,%9}, {%0,%1,%2,%3};"
        : "+f"(d[0]), "+f"(d[1]), "+f"(d[2]), "+f"(d[3])
        : "r"(a[0]), "r"(a[1]), "r"(a[2]), "r"(a[3]), "r"(b[0]), "r"(b[1]));
}
__device__ __forceinline__ void mma_bf16(float* d, const uint32_t* a, const uint32_t* b) {
    asm volatile(
        "mma.sync.aligned.m16n8k16.row.col.f32.bf16.bf16.f32 "
        "{%0,%1,%2,%3}, {%4,%5,%6,%7}, {%8,%9}, {%0,%1,%2,%3};"
        : "+f"(d[0]), "+f"(d[1]), "+f"(d[2]), "+f"(d[3])
        : "r"(a[0]), "r"(a[1]), "r"(a[2]), "r"(a[3]), "r"(b[0]), "r"(b[1]));
}

__device__ __forceinline__ uint32_t pack_bf16x2(float lo_e, float hi_e) {
    uint32_t r;
    asm("cvt.rn.bf16x2.f32 %0, %1, %2;" : "=r"(r) : "f"(hi_e), "f"(lo_e));
    return r;
}
__device__ __forceinline__ uint32_t pack_half2(float lo_e, float hi_e) {
    uint32_t r;
    asm("cvt.rn.f16x2.f32 %0, %1, %2;" : "=r"(r) : "f"(hi_e), "f"(lo_e));
    return r;
}
__device__ __forceinline__ void split_bf16(float x, float y, uint32_t &hp, uint32_t &lp) {
    hp = pack_bf16x2(x, y);
    float hx = __uint_as_float(hp << 16);
    float hy = __uint_as_float(hp & 0xffff0000u);
    lp = pack_bf16x2(x - hx, y - hy);
}

// ---------------- fused weight transpose+convert (all 4 weights) ----------
__global__ void transpose_all(const float* __restrict__ wqkv,
                              const float* __restrict__ wproj,
                              const float* __restrict__ wfc1,
                              const float* __restrict__ wfc2,
                              __half* __restrict__ oqkv, __half* __restrict__ oproj,
                              __half* __restrict__ ofc1, __half* __restrict__ ofc2) {
    const float* in; __half* out; int K, N;
    switch (blockIdx.z) {
        case 0:  in = wqkv;  out = oqkv;  K = CDIM; N = QKVC; break;
        case 1:  in = wproj; out = oproj; K = CDIM; N = CDIM; break;
        case 2:  in = wfc1;  out = ofc1;  K = CDIM; N = HID;  break;
        default: in = wfc2;  out = ofc2;  K = HID;  N = CDIM; break;
    }
    int bn = blockIdx.x << 5, bk = blockIdx.y << 5;
    if (bn >= N || bk >= K) return;
    __shared__ float t[32][33];
    int tx = threadIdx.x, ty = threadIdx.y;   // 32 x 8
#pragma unroll
    for (int i = 0; i < 4; i++)
        t[ty + i * 8][tx] = in[(size_t)(bk + ty + i * 8) * N + bn + tx];
    __syncthreads();
#pragma unroll
    for (int i = 0; i < 4; i++)
        out[(size_t)(bn + ty + i * 8) * K + bk + tx] = __float2half_rn(t[tx][ty + i * 8]);
}

// ---------------- LayerNorm (fp32 in -> fp16 out) -------------------------
__global__ void ln_kernel(const float* __restrict__ x, const float* __restrict__ w,
                          const float* __restrict__ b, __half* __restrict__ out) {
    int row = blockIdx.x;
    const float* xr = x + (size_t)row * CDIM;
    __half* orow = out + (size_t)row * CDIM;
    int t = threadIdx.x;
    float v0 = xr[t], v1 = xr[t + 256], v2 = xr[t + 512];
    float s = v0 + v1 + v2;
    float q = v0 * v0 + v1 * v1 + v2 * v2;
#pragma unroll
    for (int o = 16; o; o >>= 1) {
        s += __shfl_xor_sync(0xffffffffu, s, o);
        q += __shfl_xor_sync(0xffffffffu, q, o);
    }
    __shared__ float rs[8], rq[8];
    if ((t & 31) == 0) { rs[t >> 5] = s; rq[t >> 5] = q; }
    __syncthreads();
    if (t < 32) {
        float us = (t < 8) ? rs[t] : 0.f;
        float uq = (t < 8) ? rq[t] : 0.f;
#pragma unroll
        for (int o = 4; o; o >>= 1) {
            us += __shfl_xor_sync(0xffffffffu, us, o);
            uq += __shfl_xor_sync(0xffffffffu, uq, o);
        }
        if (t == 0) { rs[0] = us; rq[0] = uq; }
    }
    __syncthreads();
    float mu  = rs[0] * (1.f / CDIM);
    float var = rq[0] * (1.f / CDIM) - mu * mu;
    float inv = rsqrtf(var + 1e-5f);
    orow[t]       = __float2half_rn((v0 - mu) * inv * w[t]       + b[t]);
    orow[t + 256] = __float2half_rn((v1 - mu) * inv * w[t + 256] + b[t + 256]);
    orow[t + 512] = __float2half_rn((v2 - mu) * inv * w[t + 512] + b[t + 512]);
}

// ---------------- fp16 GEMM, BK=64, ldmatrix fragments --------------------
// C[M,N] = A[M,K] @ Bt[N,K]^T, fp16 ops, f32 accum, m16n8k16.
// Tile 128x128, BK=64 (128B/row, 8 chunks), 8 warps of 64x32, 4 ksteps/iter.
// Swizzle: phys_chunk = kh ^ (row & 7) -> cp.async writes and all ldmatrix
// phases conflict-free (row&7 bijection over each 8-row group).
#define GSTG 32768u
__global__ void __launch_bounds__(256, 2)
gemm_fp16(const __half* __restrict__ A, const __half* __restrict__ Bt,
          float* __restrict__ C, __half* __restrict__ C16, int N, int K,
          const float* __restrict__ bias, const float* __restrict__ resid,
          int gelu_flag) {
    extern __shared__ char smem[];
    const uint32_t sb = smem_u32(smem);
    const int tid = threadIdx.x;
    const int wid = tid >> 5, lane = tid & 31;
    const int warp_m = wid & 1, warp_n = wid >> 1;
    const int cl = lane & 3;
    const int g  = lane >> 2;
    const int bn = blockIdx.x << 7, bm = blockIdx.y << 7;
    const int nBK = K >> 6;

    float d[4][4][4];
#pragma unroll
    for (int i = 0; i < 4; i++)
#pragma unroll
        for (int j = 0; j < 4; j++)
#pragma unroll
            for (int e = 0; e < 4; e++) d[i][j][e] = 0.f;

#define LOADT(k0, buf)                                                          \
    {                                                                           \
        uint32_t base = sb + ((buf) ? GSTG : 0u);                               \
        _Pragma("unroll")                                                       \
        for (int i = 0; i < 4; i++) {                                           \
            int id = tid + (i << 8);                                            \
            int row = id >> 3, kh = id & 7;                                     \
            uint32_t dst = base + (uint32_t)(row << 7)                          \
                         + (uint32_t)((kh ^ (row & 7)) << 4);                   \
            cp_async16(dst, A + (size_t)(bm + row) * K + (k0) + (kh << 3));     \
            cp_async16(dst + 16384u,                                            \
                       Bt + (size_t)(bn + row) * K + (k0) + (kh << 3));         \
        }                                                                       \
        CP_COMMIT();                                                            \
    }

    LOADT(0, 0);
    if (nBK > 1) LOADT(64, 1);

    const int ar  = (lane & 7) + (((lane >> 3) & 1) << 3);
    const int khp = lane >> 4;
    const int rowa = warp_m * 64 + ar;
    const int rowb = warp_n * 32 + ar;
    const uint32_t sw = (uint32_t)(ar & 7);   // row&7 invariant across mi/j2

    for (int c = 0; c < nBK; c++) {
        int buf = c & 1;
        if (c == nBK - 1) asm volatile("cp.async.wait_group 0;" ::: "memory");
        else              asm volatile("cp.async.wait_group 1;" ::: "memory");
        __syncthreads();

        const uint32_t Sb = sb + (buf ? GSTG : 0u);
        const uint32_t Ab = Sb + (uint32_t)(rowa << 7);
        const uint32_t Bb = Sb + 16384u + (uint32_t)(rowb << 7);

#pragma unroll
        for (int ks = 0; ks < 4; ks++) {
            uint32_t kc = (uint32_t)((((ks << 1) + khp) ^ sw) << 4);
            uint32_t av[4][4], bv[4][2];
#pragma unroll
            for (int mi = 0; mi < 4; mi++)
                ldsm_x4(Ab + (uint32_t)(mi << 11) + kc,
                        av[mi][0], av[mi][1], av[mi][2], av[mi][3]);
#pragma unroll
            for (int j2 = 0; j2 < 2; j2++)
                ldsm_x4(Bb + (uint32_t)(j2 << 11) + kc,
                        bv[j2 * 2][0], bv[j2 * 2 + 1][0],
                        bv[j2 * 2][1], bv[j2 * 2 + 1][1]);
#pragma unroll
            for (int i = 0; i < 4; i++)
#pragma unroll
                for (int j = 0; j < 4; j++) mma_fp16(d[i][j], av[i], bv[j]);
        }
        __syncthreads();
        if (c + 2 < nBK) LOADT((c + 2) << 6, buf);
    }

    const int m0w = bm + warp_m * 64 + g;
    const int n0w = bn + warp_n * 32 + cl * 2;
#pragma unroll
    for (int i = 0; i < 4; i++) {
#pragma unroll
        for (int h = 0; h < 2; h++) {
            int row = m0w + i * 16 + h * 8;
            const float* Rrow = resid ? resid + (size_t)row * N : (const float*)0;
#pragma unroll
            for (int j = 0; j < 4; j++) {
                int col = n0w + j * 8;
                float v0 = d[i][j][h * 2 + 0];
                float v1 = d[i][j][h * 2 + 1];
                if (bias) { v0 += bias[col]; v1 += bias[col + 1]; }
                if (gelu_flag) {
                    v0 = 0.5f * v0 * (1.f + erff(v0 * 0.70710678118654752f));
                    v1 = 0.5f * v1 * (1.f + erff(v1 * 0.70710678118654752f));
                }
                if (Rrow) { v0 += Rrow[col]; v1 += Rrow[col + 1]; }
                if (C16) {
                    *(uint32_t*)&C16[(size_t)row * N + col] = pack_half2(v0, v1);
                } else {
                    *(float2*)&C[(size_t)row * N + col] = make_float2(v0, v1);
                }
            }
        }
    }
#undef LOADT
}
#define GEMM_SMEM (2 * 32768)

// ---------------- flash attention (R12/R13 body, unchanged) ---------------
#define QS 36
#define QSB 144u

__global__ void __launch_bounds__(256, 2)
flash_mma(const float* __restrict__ qkv, __half* __restrict__ att16) {
    extern __shared__ char smc[];
    uint32_t* Qhb = (uint32_t*)smc;            // [128][QS]
    uint32_t* Qlb = Qhb + 128 * QS;            // [128][QS]
    uint32_t* Khb = Qlb + 128 * QS;            // [64][QS]
    uint32_t* Klb = Khb + 64 * QS;             // [64][QS]
    uint32_t* Vth = Klb + 64 * QS;             // [64 d][QS] fp16 kv-pairs
    uint32_t* Ph  = Vth + 64 * QS;             // [128 q][QS] fp16 kv-pairs

    const int tid = threadIdx.x;
    const int wid = tid >> 5, lane = tid & 31;
    const int r = lane >> 2, cl = lane & 3;
    const int qb = blockIdx.x << 7;
    const int bh = blockIdx.y;
    const int b = bh / NHEAD, h = bh % NHEAD;
    const float* qptr = qkv + (size_t)b * SEQ * QKVC + h * HDIM;
    const float* kptr = qptr + CDIM;
    const float* vptr = qptr + 2 * CDIM;
    const uint32_t vth_sb = smem_u32(Vth);

    {
        int row = tid >> 1;
        const float* src = qptr + (size_t)(qb + row) * QKVC;
#pragma unroll
        for (int e = 0; e < 8; e++) {
            int c4 = ((tid & 1) << 3) + e;
            float4 v = *(const float4*)(src + (c4 << 2));
            v.x *= 8.f; v.y *= 8.f; v.z *= 8.f; v.w *= 8.f;
            uint32_t h0, l0, h1, l1;
            split_bf16(v.x, v.y, h0, l0);
            split_bf16(v.z, v.w, h1, l1);
            Qhb[row * QS + 2 * c4]     = h0;
            Qhb[row * QS + 2 * c4 + 1] = h1;
            Qlb[row * QS + 2 * c4]     = l0;
            Qlb[row * QS + 2 * c4 + 1] = l1;
        }
    }

    float mi0 = -3.4e38f, mi1 = -3.4e38f, li0 = 0.f, li1 = 0.f;
    float o[8][4];
#pragma unroll
    for (int j = 0; j < 8; j++)
#pragma unroll
        for (int e = 0; e < 4; e++) o[j][e] = 0.f;

    const int m0 = wid << 4;
    const int fr8 = (lane & 7) + (((lane >> 3) & 1) << 3);
    const uint32_t khf16 = (uint32_t)(lane >> 4) << 4;
    const uint32_t qoff  = (uint32_t)(m0 + fr8) * QSB + khf16;
    const uint32_t koff0 = (uint32_t)fr8 * QSB + khf16;
    const uint32_t qh_b = smem_u32(Qhb) + qoff;
    const uint32_t ql_b = smem_u32(Qlb) + qoff;
    const uint32_t kh_b = smem_u32(Khb) + koff0;
    const uint32_t kl_b = smem_u32(Klb) + koff0;
    const uint32_t ph_b = smem_u32(Ph) + qoff;
    const uint32_t vt_b = vth_sb + koff0;

    for (int t = 0; t < 16; t++) {
        __syncthreads();
        {
            int row = tid >> 2;
            const float* ksrc = kptr + (size_t)((t << 6) + row) * QKVC;
            const float* vsrc = vptr + (size_t)((t << 6) + row) * QKVC;
            uint32_t vbase = vth_sb + (uint32_t)((row >> 1) << 2) + ((row & 1) << 1);
#pragma unroll
            for (int e = 0; e < 4; e++) {
                int c4 = (tid & 3) + (e << 2);
                float4 v = *(const float4*)(ksrc + (c4 << 2));
                uint32_t h0, l0, h1, l1;
                split_bf16(v.x, v.y, h0, l0);
                split_bf16(v.z, v.w, h1, l1);
                Khb[row * QS + 2 * c4]     = h0;
                Khb[row * QS + 2 * c4 + 1] = h1;
                Klb[row * QS + 2 * c4]     = l0;
                Klb[row * QS + 2 * c4 + 1] = l1;
                float4 vv = *(const float4*)(vsrc + (c4 << 2));
                int dc = c4 << 2;
                sts16(vbase + (uint32_t)((dc + 0) * QS << 2),
                      __half_as_ushort(__float2half_rn(vv.x)));
                sts16(vbase + (uint32_t)((dc + 1) * QS << 2),
                      __half_as_ushort(__float2half_rn(vv.y)));
                sts16(vbase + (uint32_t)((dc + 2) * QS << 2),
                      __half_as_ushort(__float2half_rn(vv.z)));
                sts16(vbase + (uint32_t)((dc + 3) * QS << 2),
                      __half_as_ushort(__float2half_rn(vv.w)));
            }
        }
        __syncthreads();

        float s[8][4];
#pragma unroll
        for (int j = 0; j < 8; j++)
#pragma unroll
            for (int e = 0; e < 4; e++) s[j][e] = 0.f;

#pragma unroll
        for (int ks = 0; ks < 4; ks++) {
            uint32_t ko = (uint32_t)(ks << 5);
            uint32_t ah[4], al[4];
            ldsm_x4(qh_b + ko, ah[0], ah[1], ah[2], ah[3]);
            ldsm_x4(ql_b + ko, al[0], al[1], al[2], al[3]);
#pragma unroll
            for (int jp = 0; jp < 4; jp++) {
                uint32_t jo = (uint32_t)(jp * 16) * QSB + ko;
                uint32_t bh2[2][2], bl2[2][2];
                ldsm_x4(kh_b + jo, bh2[0][0], bh2[1][0], bh2[0][1], bh2[1][1]);
                ldsm_x4(kl_b + jo, bl2[0][0], bl2[1][0], bl2[0][1], bl2[1][1]);
#pragma unroll
                for (int jj = 0; jj < 2; jj++) {
                    int j = jp * 2 + jj;
                    mma_bf16(s[j], ah, bh2[jj]);
                    mma_bf16(s[j], al, bh2[jj]);
                    mma_bf16(s[j], ah, bl2[jj]);
                }
            }
        }

        float mx0 = s[0][0], mx1 = s[0][2];
#pragma unroll
        for (int j = 0; j < 8; j++) {
            mx0 = fmaxf(mx0, fmaxf(s[j][0], s[j][1]));
            mx1 = fmaxf(mx1, fmaxf(s[j][2], s[j][3]));
        }
        mx0 = fmaxf(mx0, __shfl_xor_sync(0xffffffffu, mx0, 1));
        mx0 = fmaxf(mx0, __shfl_xor_sync(0xffffffffu, mx0, 2));
        mx1 = fmaxf(mx1, __shfl_xor_sync(0xffffffffu, mx1, 1));
        mx1 = fmaxf(mx1, __shfl_xor_sync(0xffffffffu, mx1, 2));
        float mn0 = fmaxf(mi0, mx0), mn1 = fmaxf(mi1, mx1);
        float sc0 = __expf(mi0 - mn0), sc1 = __expf(mi1 - mn1);
        mi0 = mn0; mi1 = mn1;
        float sum0 = 0.f, sum1 = 0.f;
#pragma unroll
        for (int j = 0; j < 8; j++) {
            s[j][0] = __expf(s[j][0] - mn0);
            s[j][1] = __expf(s[j][1] - mn0);
            s[j][2] = __expf(s[j][2] - mn1);
            s[j][3] = __expf(s[j][3] - mn1);
            sum0 += s[j][0] + s[j][1];
            sum1 += s[j][2] + s[j][3];
        }
        sum0 += __shfl_xor_sync(0xffffffffu, sum0, 1);
        sum0 += __shfl_xor_sync(0xffffffffu, sum0, 2);
        sum1 += __shfl_xor_sync(0xffffffffu, sum1, 1);
        sum1 += __shfl_xor_sync(0xffffffffu, sum1, 2);
        li0 = li0 * sc0 + sum0;
        li1 = li1 * sc1 + sum1;
#pragma unroll
        for (int j = 0; j < 8; j++) {
            o[j][0] *= sc0; o[j][1] *= sc0;
            o[j][2] *= sc1; o[j][3] *= sc1;
        }

#pragma unroll
        for (int j = 0; j < 8; j++) {
            Ph[(m0 + r) * QS + (j << 2) + cl]     = pack_half2(s[j][0], s[j][1]);
            Ph[(m0 + r + 8) * QS + (j << 2) + cl] = pack_half2(s[j][2], s[j][3]);
        }
        __syncwarp();

#pragma unroll
        for (int ks = 0; ks < 4; ks++) {
            uint32_t ko = (uint32_t)(ks << 5);
            uint32_t a[4];
            ldsm_x4(ph_b + ko, a[0], a[1], a[2], a[3]);
#pragma unroll
            for (int jp = 0; jp < 4; jp++) {
                uint32_t jo = (uint32_t)(jp * 16) * QSB + ko;
                uint32_t b2[2][2];
                ldsm_x4(vt_b + jo, b2[0][0], b2[1][0], b2[0][1], b2[1][1]);
                mma_fp16(o[jp * 2 + 0], a, b2[0]);
                mma_fp16(o[jp * 2 + 1], a, b2[1]);
            }
        }
    }

    {
        float inv0 = 1.f / li0, inv1 = 1.f / li1;
        __half* o0 = att16 + ((size_t)(b * SEQ + qb + m0 + r)) * CDIM + h * HDIM;
        __half* o1 = o0 + 8 * CDIM;
#pragma unroll
        for (int j = 0; j < 8; j++) {
            int col = (j << 3) + (cl << 1);
            *(uint32_t*)&o0[col] = pack_half2(o[j][0] * inv0, o[j][1] * inv0);
            *(uint32_t*)&o1[col] = pack_half2(o[j][2] * inv1, o[j][3] * inv1);
        }
    }
}
#define FLASH_SMEM ((128 + 128 + 64 + 64 + 64 + 128) * QS * 4)

// ---------------- launch --------------------------------------------------
extern "C" void kernel_launch(void* const* d_in, const int* in_sizes, int n_in,
                              void* d_out, int out_size) {
    const float* x     = (const float*)d_in[0];
    const float* ln1w  = (const float*)d_in[1];
    const float* ln1b  = (const float*)d_in[2];
    const float* ln2w  = (const float*)d_in[3];
    const float* ln2b  = (const float*)d_in[4];
    const float* wqkv  = (const float*)d_in[5];
    const float* wproj = (const float*)d_in[6];
    const float* wfc1  = (const float*)d_in[7];
    const float* bfc1  = (const float*)d_in[8];
    const float* wfc2  = (const float*)d_in[9];
    const float* bfc2  = (const float*)d_in[10];
    float* out = (float*)d_out;

    __half *p_h16, *p_att16, *p_fc1h, *p_wqkv_h, *p_wproj_h, *p_wfc1_h, *p_wfc2_h;
    float *p_qkv, *p_x1;
    cudaGetSymbolAddress((void**)&p_h16, g_h16);
    cudaGetSymbolAddress((void**)&p_qkv, g_qkv);
    cudaGetSymbolAddress((void**)&p_att16, g_att16);
    cudaGetSymbolAddress((void**)&p_x1, g_x1);
    cudaGetSymbolAddress((void**)&p_fc1h, g_fc1h);
    cudaGetSymbolAddress((void**)&p_wqkv_h, g_wqkv_h);
    cudaGetSymbolAddress((void**)&p_wproj_h, g_wproj_h);
    cudaGetSymbolAddress((void**)&p_wfc1_h, g_wfc1_h);
    cudaGetSymbolAddress((void**)&p_wfc2_h, g_wfc2_h);

    cudaFuncSetAttribute(flash_mma, cudaFuncAttributeMaxDynamicSharedMemorySize,
                         FLASH_SMEM);
    cudaFuncSetAttribute(gemm_fp16, cudaFuncAttributeMaxDynamicSharedMemorySize,
                         GEMM_SMEM);

    // fused weight transposes (one launch)
    transpose_all<<<dim3(QKVC / 32, CDIM / 32, 4), dim3(32, 8)>>>(
        wqkv, wproj, wfc1, wfc2, p_wqkv_h, p_wproj_h, p_wfc1_h, p_wfc2_h);

    // 1) h = LN1(x)  (fp16 out)
    ln_kernel<<<TOKS, 256>>>(x, ln1w, ln1b, p_h16);
    // 2) qkv = h @ w_qkv  (fp32 out, feeds flash)
    gemm_fp16<<<dim3(QKVC / 128, TOKS / 128), 256, GEMM_SMEM>>>(
        p_h16, p_wqkv_h, p_qkv, nullptr, QKVC, CDIM, nullptr, nullptr, 0);
    // 3-5) fused attention (att out fp16)
    flash_mma<<<dim3(SEQ / 128, NBH), 256, FLASH_SMEM>>>(p_qkv, p_att16);
    // 6) x1 = x + att @ w_proj  (fp32 out)
    gemm_fp16<<<dim3(CDIM / 128, TOKS / 128), 256, GEMM_SMEM>>>(
        p_att16, p_wproj_h, p_x1, nullptr, CDIM, CDIM, nullptr, x, 0);
    // 7) h = LN2(x1)  (fp16 out)
    ln_kernel<<<TOKS, 256>>>(p_x1, ln2w, ln2b, p_h16);
    // 8) fc1 = gelu(h @ w_fc1 + b_fc1)  (fp16 out)
    gemm_fp16<<<dim3(HID / 128, TOKS / 128), 256, GEMM_SMEM>>>(
        p_h16, p_wfc1_h, nullptr, p_fc1h, HID, CDIM, bfc1, nullptr, 1);
    // 9) out = x1 + fc1 @ w_fc2 + b_fc2  (fp32 out)
    gemm_fp16<<<dim3(CDIM / 128, TOKS / 128), 256, GEMM_SMEM>>>(
        p_fc1h, p_wfc2_h, out, nullptr, CDIM, HID, bfc2, p_x1, 0);
}

// round 16
// speedup vs baseline: 1.0982x; 1.0582x over previous
#include <cuda_runtime.h>
#include <cuda_fp16.h>
#include <math.h>
#include <stddef.h>
#include <stdint.h>

// ---------------- problem constants ----------------
#define TOKS   8192
#define CDIM   768
#define HID    384
#define NHEAD  12
#define HDIM   64
#define SEQ    1024
#define QKVC   2304
#define NBH    96

// ---------------- scratch ---------------------------
__device__ __half   g_h16[(size_t)TOKS * CDIM];
__device__ float    g_q[(size_t)TOKS * CDIM];          // q (fp32)
__device__ uint32_t g_khi[(size_t)TOKS * (CDIM / 2)];  // k bf16-hi pairs
__device__ uint32_t g_klo[(size_t)TOKS * (CDIM / 2)];  // k bf16-lo pairs
__device__ uint32_t g_v16[(size_t)TOKS * (CDIM / 2)];  // v fp16 pairs
__device__ __half   g_att16[(size_t)TOKS * CDIM];
__device__ float    g_x1[(size_t)TOKS * CDIM];
__device__ __half   g_fc1h[(size_t)TOKS * HID];
__device__ __half   g_wqkv_h[(size_t)QKVC * CDIM];
__device__ __half   g_wproj_h[(size_t)CDIM * CDIM];
__device__ __half   g_wfc1_h[(size_t)HID * CDIM];
__device__ __half   g_wfc2_h[(size_t)CDIM * HID];

typedef unsigned long long u64;

// ---------------- helpers -----------------------
__device__ __forceinline__ uint32_t smem_u32(const void* p) {
    uint32_t a;
    asm("{ .reg .u64 t; cvta.to.shared.u64 t, %1; cvt.u32.u64 %0, t; }" : "=r"(a) : "l"(p));
    return a;
}
__device__ __forceinline__ void cp_async16(uint32_t dst, const void* src) {
    asm volatile("cp.async.cg.shared.global [%0], [%1], 16;" :: "r"(dst), "l"(src));
}
#define CP_COMMIT() asm volatile("cp.async.commit_group;" ::: "memory")

__device__ __forceinline__ void ldsm_x4(uint32_t addr, uint32_t &r0, uint32_t &r1,
                                        uint32_t &r2, uint32_t &r3) {
    asm volatile("ldmatrix.sync.aligned.m8n8.x4.shared.b16 {%0,%1,%2,%3}, [%4];"
                 : "=r"(r0), "=r"(r1), "=r"(r2), "=r"(r3) : "r"(addr));
}
__device__ __forceinline__ void ldsm_x4_t(uint32_t addr, uint32_t &r0, uint32_t &r1,
                                          uint32_t &r2, uint32_t &r3) {
    asm volatile("ldmatrix.sync.aligned.m8n8.x4.trans.shared.b16 {%0,%1,%2,%3}, [%4];"
                 : "=r"(r0), "=r"(r1), "=r"(r2), "=r"(r3) : "r"(addr));
}

__device__ __forceinline__ void mma_fp16(float* d, const uint32_t* a, const uint32_t* b) {
    asm volatile(
        "mma.sync.aligned.m16n8k16.row.col.f32.f16.f16.f32 "
        "{%0,%1,%2,%3}, {%4,%5,%6,%7}, {%8,%9}, {%0,%1,%2,%3};"
        : "+f"(d[0]), "+f"(d[1]), "+f"(d[2]), "+f"(d[3])
        : "r"(a[0]), "r"(a[1]), "r"(a[2]), "r"(a[3]), "r"(b[0]), "r"(b[1]));
}
__device__ __forceinline__ void mma_bf16(float* d, const uint32_t* a, const uint32_t* b) {
    asm volatile(
        "mma.sync.aligned.m16n8k16.row.col.f32.bf16.bf16.f32 "
        "{%0,%1,%2,%3}, {%4,%5,%6,%7}, {%8,%9}, {%0,%1,%2,%3};"
        : "+f"(d[0]), "+f"(d[1]), "+f"(d[2]), "+f"(d[3])
        : "r"(a[0]), "r"(a[1]), "r"(a[2]), "r"(a[3]), "r"(b[0]), "r"(b[1]));
}

__device__ __forceinline__ uint32_t pack_bf16x2(float lo_e, float hi_e) {
    uint32_t r;
    asm("cvt.rn.bf16x2.f32 %0, %1, %2;" : "=r"(r) : "f"(hi_e), "f"(lo_e));
    return r;
}
__device__ __forceinline__ uint32_t pack_half2(float lo_e, float hi_e) {
    uint32_t r;
    asm("cvt.rn.f16x2.f32 %0, %1, %2;" : "=r"(r) : "f"(hi_e), "f"(lo_e));
    return r;
}
__device__ __forceinline__ void split_bf16(float x, float y, uint32_t &hp, uint32_t &lp) {
    hp = pack_bf16x2(x, y);
    float hx = __uint_as_float(hp << 16);
    float hy = __uint_as_float(hp & 0xffff0000u);
    lp = pack_bf16x2(x - hx, y - hy);
}

// ---------------- fused weight transpose+convert (all 4 weights) ----------
__global__ void transpose_all(const float* __restrict__ wqkv,
                              const float* __restrict__ wproj,
                              const float* __restrict__ wfc1,
                              const float* __restrict__ wfc2,
                              __half* __restrict__ oqkv, __half* __restrict__ oproj,
                              __half* __restrict__ ofc1, __half* __restrict__ ofc2) {
    const float* in; __half* out; int K, N;
    switch (blockIdx.z) {
        case 0:  in = wqkv;  out = oqkv;  K = CDIM; N = QKVC; break;
        case 1:  in = wproj; out = oproj; K = CDIM; N = CDIM; break;
        case 2:  in = wfc1;  out = ofc1;  K = CDIM; N = HID;  break;
        default: in = wfc2;  out = ofc2;  K = HID;  N = CDIM; break;
    }
    int bn = blockIdx.x << 5, bk = blockIdx.y << 5;
    if (bn >= N || bk >= K) return;
    __shared__ float t[32][33];
    int tx = threadIdx.x, ty = threadIdx.y;
#pragma unroll
    for (int i = 0; i < 4; i++)
        t[ty + i * 8][tx] = in[(size_t)(bk + ty + i * 8) * N + bn + tx];
    __syncthreads();
#pragma unroll
    for (int i = 0; i < 4; i++)
        out[(size_t)(bn + ty + i * 8) * K + bk + tx] = __float2half_rn(t[tx][ty + i * 8]);
}

// ---------------- LayerNorm (fp32 in -> fp16 out) -------------------------
__global__ void ln_kernel(const float* __restrict__ x, const float* __restrict__ w,
                          const float* __restrict__ b, __half* __restrict__ out) {
    int row = blockIdx.x;
    const float* xr = x + (size_t)row * CDIM;
    __half* orow = out + (size_t)row * CDIM;
    int t = threadIdx.x;
    float v0 = xr[t], v1 = xr[t + 256], v2 = xr[t + 512];
    float s = v0 + v1 + v2;
    float q = v0 * v0 + v1 * v1 + v2 * v2;
#pragma unroll
    for (int o = 16; o; o >>= 1) {
        s += __shfl_xor_sync(0xffffffffu, s, o);
        q += __shfl_xor_sync(0xffffffffu, q, o);
    }
    __shared__ float rs[8], rq[8];
    if ((t & 31) == 0) { rs[t >> 5] = s; rq[t >> 5] = q; }
    __syncthreads();
    if (t < 32) {
        float us = (t < 8) ? rs[t] : 0.f;
        float uq = (t < 8) ? rq[t] : 0.f;
#pragma unroll
        for (int o = 4; o; o >>= 1) {
            us += __shfl_xor_sync(0xffffffffu, us, o);
            uq += __shfl_xor_sync(0xffffffffu, uq, o);
        }
        if (t == 0) { rs[0] = us; rq[0] = uq; }
    }
    __syncthreads();
    float mu  = rs[0] * (1.f / CDIM);
    float var = rq[0] * (1.f / CDIM) - mu * mu;
    float inv = rsqrtf(var + 1e-5f);
    orow[t]       = __float2half_rn((v0 - mu) * inv * w[t]       + b[t]);
    orow[t + 256] = __float2half_rn((v1 - mu) * inv * w[t + 256] + b[t + 256]);
    orow[t + 512] = __float2half_rn((v2 - mu) * inv * w[t + 512] + b[t + 512]);
}

// ---------------- fp16 GEMM, BK=64, ldmatrix (R14) + qkv-split epilogue ---
#define GSTG 32768u
__global__ void __launch_bounds__(256, 2)
gemm_fp16(const __half* __restrict__ A, const __half* __restrict__ Bt,
          float* __restrict__ C, __half* __restrict__ C16, int N, int K,
          const float* __restrict__ bias, const float* __restrict__ resid,
          int gelu_flag, int qkv_mode,
          float* __restrict__ Cq, uint32_t* __restrict__ Khi,
          uint32_t* __restrict__ Klo, uint32_t* __restrict__ V16) {
    extern __shared__ char smem[];
    const uint32_t sb = smem_u32(smem);
    const int tid = threadIdx.x;
    const int wid = tid >> 5, lane = tid & 31;
    const int warp_m = wid & 1, warp_n = wid >> 1;
    const int cl = lane & 3;
    const int g  = lane >> 2;
    const int bn = blockIdx.x << 7, bm = blockIdx.y << 7;
    const int nBK = K >> 6;

    float d[4][4][4];
#pragma unroll
    for (int i = 0; i < 4; i++)
#pragma unroll
        for (int j = 0; j < 4; j++)
#pragma unroll
            for (int e = 0; e < 4; e++) d[i][j][e] = 0.f;

#define LOADT(k0, buf)                                                          \
    {                                                                           \
        uint32_t base = sb + ((buf) ? GSTG : 0u);                               \
        _Pragma("unroll")                                                       \
        for (int i = 0; i < 4; i++) {                                           \
            int id = tid + (i << 8);                                            \
            int row = id >> 3, kh = id & 7;                                     \
            uint32_t dst = base + (uint32_t)(row << 7)                          \
                         + (uint32_t)((kh ^ (row & 7)) << 4);                   \
            cp_async16(dst, A + (size_t)(bm + row) * K + (k0) + (kh << 3));     \
            cp_async16(dst + 16384u,                                            \
                       Bt + (size_t)(bn + row) * K + (k0) + (kh << 3));         \
        }                                                                       \
        CP_COMMIT();                                                            \
    }

    LOADT(0, 0);
    if (nBK > 1) LOADT(64, 1);

    const int ar  = (lane & 7) + (((lane >> 3) & 1) << 3);
    const int khp = lane >> 4;
    const int rowa = warp_m * 64 + ar;
    const int rowb = warp_n * 32 + ar;
    const uint32_t sw = (uint32_t)(ar & 7);

    for (int c = 0; c < nBK; c++) {
        int buf = c & 1;
        if (c == nBK - 1) asm volatile("cp.async.wait_group 0;" ::: "memory");
        else              asm volatile("cp.async.wait_group 1;" ::: "memory");
        __syncthreads();

        const uint32_t Sb = sb + (buf ? GSTG : 0u);
        const uint32_t Ab = Sb + (uint32_t)(rowa << 7);
        const uint32_t Bb = Sb + 16384u + (uint32_t)(rowb << 7);

#pragma unroll
        for (int ks = 0; ks < 4; ks++) {
            uint32_t kc = (uint32_t)((((ks << 1) + khp) ^ sw) << 4);
            uint32_t av[4][4], bv[4][2];
#pragma unroll
            for (int mi = 0; mi < 4; mi++)
                ldsm_x4(Ab + (uint32_t)(mi << 11) + kc,
                        av[mi][0], av[mi][1], av[mi][2], av[mi][3]);
#pragma unroll
            for (int j2 = 0; j2 < 2; j2++)
                ldsm_x4(Bb + (uint32_t)(j2 << 11) + kc,
                        bv[j2 * 2][0], bv[j2 * 2 + 1][0],
                        bv[j2 * 2][1], bv[j2 * 2 + 1][1]);
#pragma unroll
            for (int i = 0; i < 4; i++)
#pragma unroll
                for (int j = 0; j < 4; j++) mma_fp16(d[i][j], av[i], bv[j]);
        }
        __syncthreads();
        if (c + 2 < nBK) LOADT((c + 2) << 6, buf);
    }

    const int m0w = bm + warp_m * 64 + g;
    const int n0w = bn + warp_n * 32 + cl * 2;
#pragma unroll
    for (int i = 0; i < 4; i++) {
#pragma unroll
        for (int h = 0; h < 2; h++) {
            int row = m0w + i * 16 + h * 8;
            const float* Rrow = resid ? resid + (size_t)row * N : (const float*)0;
#pragma unroll
            for (int j = 0; j < 4; j++) {
                int col = n0w + j * 8;
                float v0 = d[i][j][h * 2 + 0];
                float v1 = d[i][j][h * 2 + 1];
                if (bias) { v0 += bias[col]; v1 += bias[col + 1]; }
                if (gelu_flag) {
                    v0 = 0.5f * v0 * (1.f + erff(v0 * 0.70710678118654752f));
                    v1 = 0.5f * v1 * (1.f + erff(v1 * 0.70710678118654752f));
                }
                if (Rrow) { v0 += Rrow[col]; v1 += Rrow[col + 1]; }
                if (qkv_mode) {
                    if (bn < CDIM) {
                        *(float2*)&Cq[(size_t)row * CDIM + col] = make_float2(v0, v1);
                    } else if (bn < 2 * CDIM) {
                        uint32_t hp, lp;
                        split_bf16(v0, v1, hp, lp);
                        size_t idx = (size_t)row * (CDIM / 2) + ((col - CDIM) >> 1);
                        Khi[idx] = hp;
                        Klo[idx] = lp;
                    } else {
                        V16[(size_t)row * (CDIM / 2) + ((col - 2 * CDIM) >> 1)] =
                            pack_half2(v0, v1);
                    }
                } else if (C16) {
                    *(uint32_t*)&C16[(size_t)row * N + col] = pack_half2(v0, v1);
                } else {
                    *(float2*)&C[(size_t)row * N + col] = make_float2(v0, v1);
                }
            }
        }
    }
#undef LOADT
}
#define GEMM_SMEM (2 * 32768)

// ---------------- flash attention: pre-split K/V, cp.async pipeline -------
#define QS 36
#define QSB 144u
#define KVSTG 8192u

__global__ void __launch_bounds__(256, 2)
flash_mma(const float* __restrict__ q, const uint32_t* __restrict__ khi,
          const uint32_t* __restrict__ klo, const uint32_t* __restrict__ v16,
          __half* __restrict__ att16) {
    extern __shared__ char smc[];
    uint32_t* Qhb = (uint32_t*)smc;            // [128][QS]
    uint32_t* Qlb = Qhb + 128 * QS;            // [128][QS]
    uint32_t* Ph  = Qlb + 128 * QS;            // [128][QS]
    char* Kh0 = (char*)(Ph + 128 * QS);        // 2 x 8192
    char* Kl0 = Kh0 + 2 * KVSTG;               // 2 x 8192
    char* Vv0 = Kl0 + 2 * KVSTG;               // 2 x 8192

    const int tid = threadIdx.x;
    const int wid = tid >> 5, lane = tid & 31;
    const int r = lane >> 2, cl = lane & 3;
    const int qb = blockIdx.x << 7;
    const int bh = blockIdx.y;
    const int b = bh / NHEAD, h = bh % NHEAD;

    const uint32_t kh_sb = smem_u32(Kh0);
    const uint32_t kl_sb = smem_u32(Kl0);
    const uint32_t vv_sb = smem_u32(Vv0);

    const uint32_t* kh_g = khi + (size_t)(b * SEQ) * (CDIM / 2) + h * (HDIM / 2);
    const uint32_t* kl_g = klo + (size_t)(b * SEQ) * (CDIM / 2) + h * (HDIM / 2);
    const uint32_t* vv_g = v16 + (size_t)(b * SEQ) * (CDIM / 2) + h * (HDIM / 2);

    const int lrow = tid >> 2;
    const int lc2 = (tid & 3) << 1;

#define LOADKV(t, stg)                                                          \
    {                                                                           \
        size_t gro = (size_t)(((t) << 6) + lrow) * (CDIM / 2);                  \
        uint32_t so = (uint32_t)(stg) * KVSTG + (uint32_t)(lrow << 7);          \
        _Pragma("unroll")                                                       \
        for (int e = 0; e < 2; e++) {                                           \
            int ch = lc2 + e;                                                   \
            uint32_t sws = so + (uint32_t)((ch ^ (lrow & 7)) << 4);             \
            cp_async16(kh_sb + sws, kh_g + gro + (ch << 2));                    \
            cp_async16(kl_sb + sws, kl_g + gro + (ch << 2));                    \
            cp_async16(vv_sb + sws, vv_g + gro + (ch << 2));                    \
        }                                                                       \
        CP_COMMIT();                                                            \
    }

    LOADKV(0, 0);

    // ---- load Q (fp32, x8 scale), split bf16 hi/lo pairs (once) ----
    {
        int row = tid >> 1;
        const float* src = q + (size_t)(b * SEQ + qb + row) * CDIM + h * HDIM;
#pragma unroll
        for (int e = 0; e < 8; e++) {
            int c4 = ((tid & 1) << 3) + e;
            float2 v = *(const float2*)(src + (c4 << 1));
            v.x *= 8.f; v.y *= 8.f;
            uint32_t hp, lp;
            split_bf16(v.x, v.y, hp, lp);
            Qhb[row * QS + c4] = hp;
            Qlb[row * QS + c4] = lp;
        }
#pragma unroll
        for (int e = 0; e < 8; e++) {
            int c4 = 16 + ((tid & 1) << 3) + e;
            float2 v = *(const float2*)(src + (c4 << 1));
            v.x *= 8.f; v.y *= 8.f;
            uint32_t hp, lp;
            split_bf16(v.x, v.y, hp, lp);
            Qhb[row * QS + c4] = hp;
            Qlb[row * QS + c4] = lp;
        }
    }

    float mi0 = -3.4e38f, mi1 = -3.4e38f, li0 = 0.f, li1 = 0.f;
    float o[8][4];
#pragma unroll
    for (int j = 0; j < 8; j++)
#pragma unroll
        for (int e = 0; e < 4; e++) o[j][e] = 0.f;

    const int m0 = wid << 4;
    const int fr8 = (lane & 7) + (((lane >> 3) & 1) << 3);
    const uint32_t khf16 = (uint32_t)(lane >> 4) << 4;
    const uint32_t qh_b = smem_u32(Qhb) + (uint32_t)(m0 + fr8) * QSB + khf16;
    const uint32_t ql_b = smem_u32(Qlb) + (uint32_t)(m0 + fr8) * QSB + khf16;
    const uint32_t ph_b = smem_u32(Ph) + (uint32_t)(m0 + fr8) * QSB + khf16;
    const uint32_t sw7 = (uint32_t)(lane & 7);
    const int khpi = lane >> 4;
    const uint32_t kfr_off = (uint32_t)(fr8 << 7);
    const uint32_t vrow_off = (uint32_t)(((lane >> 4) << 3) + (lane & 7)) << 7;
    const int vch = (lane >> 3) & 1;

    for (int t = 0; t < 16; t++) {
        int stg = t & 1;
        asm volatile("cp.async.wait_group 0;" ::: "memory");
        __syncthreads();
        if (t + 1 < 16) LOADKV(t + 1, stg ^ 1);

        const uint32_t khb = kh_sb + (uint32_t)stg * KVSTG + kfr_off;
        const uint32_t klb = kl_sb + (uint32_t)stg * KVSTG + kfr_off;
        const uint32_t vvb = vv_sb + (uint32_t)stg * KVSTG + vrow_off;

        // ---- S = Q K^T (bf16x3, m16n8k16) ----
        float s[8][4];
#pragma unroll
        for (int j = 0; j < 8; j++)
#pragma unroll
            for (int e = 0; e < 4; e++) s[j][e] = 0.f;

#pragma unroll
        for (int ks = 0; ks < 4; ks++) {
            uint32_t ko = (uint32_t)(ks << 5);
            uint32_t kc = (uint32_t)((((ks << 1) + khpi) ^ sw7) << 4);
            uint32_t ah[4], al[4];
            ldsm_x4(qh_b + ko, ah[0], ah[1], ah[2], ah[3]);
            ldsm_x4(ql_b + ko, al[0], al[1], al[2], al[3]);
#pragma unroll
            for (int jp = 0; jp < 4; jp++) {
                uint32_t jo = (uint32_t)(jp << 11);
                uint32_t bh2[2][2], bl2[2][2];
                ldsm_x4(khb + jo + kc, bh2[0][0], bh2[1][0], bh2[0][1], bh2[1][1]);
                ldsm_x4(klb + jo + kc, bl2[0][0], bl2[1][0], bl2[0][1], bl2[1][1]);
#pragma unroll
                for (int jj = 0; jj < 2; jj++) {
                    int j = jp * 2 + jj;
                    mma_bf16(s[j], ah, bh2[jj]);
                    mma_bf16(s[j], al, bh2[jj]);
                    mma_bf16(s[j], ah, bl2[jj]);
                }
            }
        }

        // ---- online softmax (rows m0+r and m0+r+8) ----
        float mx0 = s[0][0], mx1 = s[0][2];
#pragma unroll
        for (int j = 0; j < 8; j++) {
            mx0 = fmaxf(mx0, fmaxf(s[j][0], s[j][1]));
            mx1 = fmaxf(mx1, fmaxf(s[j][2], s[j][3]));
        }
        mx0 = fmaxf(mx0, __shfl_xor_sync(0xffffffffu, mx0, 1));
        mx0 = fmaxf(mx0, __shfl_xor_sync(0xffffffffu, mx0, 2));
        mx1 = fmaxf(mx1, __shfl_xor_sync(0xffffffffu, mx1, 1));
        mx1 = fmaxf(mx1, __shfl_xor_sync(0xffffffffu, mx1, 2));
        float mn0 = fmaxf(mi0, mx0), mn1 = fmaxf(mi1, mx1);
        float sc0 = __expf(mi0 - mn0), sc1 = __expf(mi1 - mn1);
        mi0 = mn0; mi1 = mn1;
        float sum0 = 0.f, sum1 = 0.f;
#pragma unroll
        for (int j = 0; j < 8; j++) {
            s[j][0] = __expf(s[j][0] - mn0);
            s[j][1] = __expf(s[j][1] - mn0);
            s[j][2] = __expf(s[j][2] - mn1);
            s[j][3] = __expf(s[j][3] - mn1);
            sum0 += s[j][0] + s[j][1];
            sum1 += s[j][2] + s[j][3];
        }
        sum0 += __shfl_xor_sync(0xffffffffu, sum0, 1);
        sum0 += __shfl_xor_sync(0xffffffffu, sum0, 2);
        sum1 += __shfl_xor_sync(0xffffffffu, sum1, 1);
        sum1 += __shfl_xor_sync(0xffffffffu, sum1, 2);
        li0 = li0 * sc0 + sum0;
        li1 = li1 * sc1 + sum1;
#pragma unroll
        for (int j = 0; j < 8; j++) {
            o[j][0] *= sc0; o[j][1] *= sc0;
            o[j][2] *= sc1; o[j][3] *= sc1;
        }

        // ---- store P as fp16 pairs (warp-private rows) ----
#pragma unroll
        for (int j = 0; j < 8; j++) {
            Ph[(m0 + r) * QS + (j << 2) + cl]     = pack_half2(s[j][0], s[j][1]);
            Ph[(m0 + r + 8) * QS + (j << 2) + cl] = pack_half2(s[j][2], s[j][3]);
        }
        __syncwarp();

        // ---- O += P @ V (fp16 m16n8k16), V via ldmatrix.trans ----
#pragma unroll
        for (int ks = 0; ks < 4; ks++) {
            uint32_t ko = (uint32_t)(ks << 5);
            uint32_t a[4];
            ldsm_x4(ph_b + ko, a[0], a[1], a[2], a[3]);
            uint32_t vrow = vvb + (uint32_t)(ks << 11);
#pragma unroll
            for (int jp = 0; jp < 4; jp++) {
                uint32_t vc = (uint32_t)((((jp << 1) + vch) ^ sw7) << 4);
                uint32_t b2[2][2];
                ldsm_x4_t(vrow + vc, b2[0][0], b2[1][0], b2[0][1], b2[1][1]);
                mma_fp16(o[jp * 2 + 0], a, b2[0]);
                mma_fp16(o[jp * 2 + 1], a, b2[1]);
            }
        }
        __syncthreads();
    }

    // ---- epilogue: O / l -> att16 in [B,N,C] ----
    {
        float inv0 = 1.f / li0, inv1 = 1.f / li1;
        __half* o0 = att16 + ((size_t)(b * SEQ + qb + m0 + r)) * CDIM + h * HDIM;
        __half* o1 = o0 + 8 * CDIM;
#pragma unroll
        for (int j = 0; j < 8; j++) {
            int col = (j << 3) + (cl << 1);
            *(uint32_t*)&o0[col] = pack_half2(o[j][0] * inv0, o[j][1] * inv0);
            *(uint32_t*)&o1[col] = pack_half2(o[j][2] * inv1, o[j][3] * inv1);
        }
    }
#undef LOADKV
}
#define FLASH_SMEM (3 * 128 * QS * 4 + 3 * 2 * KVSTG)

// ---------------- launch --------------------------------------------------
extern "C" void kernel_launch(void* const* d_in, const int* in_sizes, int n_in,
                              void* d_out, int out_size) {
    const float* x     = (const float*)d_in[0];
    const float* ln1w  = (const float*)d_in[1];
    const float* ln1b  = (const float*)d_in[2];
    const float* ln2w  = (const float*)d_in[3];
    const float* ln2b  = (const float*)d_in[4];
    const float* wqkv  = (const float*)d_in[5];
    const float* wproj = (const float*)d_in[6];
    const float* wfc1  = (const float*)d_in[7];
    const float* bfc1  = (const float*)d_in[8];
    const float* wfc2  = (const float*)d_in[9];
    const float* bfc2  = (const float*)d_in[10];
    float* out = (float*)d_out;

    __half *p_h16, *p_att16, *p_fc1h, *p_wqkv_h, *p_wproj_h, *p_wfc1_h, *p_wfc2_h;
    float *p_q, *p_x1;
    uint32_t *p_khi, *p_klo, *p_v16;
    cudaGetSymbolAddress((void**)&p_h16, g_h16);
    cudaGetSymbolAddress((void**)&p_q, g_q);
    cudaGetSymbolAddress((void**)&p_khi, g_khi);
    cudaGetSymbolAddress((void**)&p_klo, g_klo);
    cudaGetSymbolAddress((void**)&p_v16, g_v16);
    cudaGetSymbolAddress((void**)&p_att16, g_att16);
    cudaGetSymbolAddress((void**)&p_x1, g_x1);
    cudaGetSymbolAddress((void**)&p_fc1h, g_fc1h);
    cudaGetSymbolAddress((void**)&p_wqkv_h, g_wqkv_h);
    cudaGetSymbolAddress((void**)&p_wproj_h, g_wproj_h);
    cudaGetSymbolAddress((void**)&p_wfc1_h, g_wfc1_h);
    cudaGetSymbolAddress((void**)&p_wfc2_h, g_wfc2_h);

    cudaFuncSetAttribute(flash_mma, cudaFuncAttributeMaxDynamicSharedMemorySize,
                         FLASH_SMEM);
    cudaFuncSetAttribute(gemm_fp16, cudaFuncAttributeMaxDynamicSharedMemorySize,
                         GEMM_SMEM);

    transpose_all<<<dim3(QKVC / 32, CDIM / 32, 4), dim3(32, 8)>>>(
        wqkv, wproj, wfc1, wfc2, p_wqkv_h, p_wproj_h, p_wfc1_h, p_wfc2_h);

    // 1) h = LN1(x)
    ln_kernel<<<TOKS, 256>>>(x, ln1w, ln1b, p_h16);
    // 2) qkv GEMM with split epilogue: q fp32, k bf16 hi/lo, v fp16
    gemm_fp16<<<dim3(QKVC / 128, TOKS / 128), 256, GEMM_SMEM>>>(
        p_h16, p_wqkv_h, nullptr, nullptr, QKVC, CDIM, nullptr, nullptr, 0,
        1, p_q, p_khi, p_klo, p_v16);
    // 3-5) fused attention
    flash_mma<<<dim3(SEQ / 128, NBH), 256, FLASH_SMEM>>>(
        p_q, p_khi, p_klo, p_v16, p_att16);
    // 6) x1 = x + att @ w_proj
    gemm_fp16<<<dim3(CDIM / 128, TOKS / 128), 256, GEMM_SMEM>>>(
        p_att16, p_wproj_h, p_x1, nullptr, CDIM, CDIM, nullptr, x, 0,
        0, nullptr, nullptr, nullptr, nullptr);
    // 7) h = LN2(x1)
    ln_kernel<<<TOKS, 256>>>(p_x1, ln2w, ln2b, p_h16);
    // 8) fc1 = gelu(h @ w_fc1 + b_fc1)
    gemm_fp16<<<dim3(HID / 128, TOKS / 128), 256, GEMM_SMEM>>>(
        p_h16, p_wfc1_h, nullptr, p_fc1h, HID, CDIM, bfc1, nullptr, 1,
        0, nullptr, nullptr, nullptr, nullptr);
    // 9) out = x1 + fc1 @ w_fc2 + b_fc2
    gemm_fp16<<<dim3(CDIM / 128, TOKS / 128), 256, GEMM_SMEM>>>(
        p_fc1h, p_wfc2_h, out, nullptr, CDIM, HID, bfc2, p_x1, 0,
        0, nullptr, nullptr, nullptr, nullptr);
}

// round 17
// speedup vs baseline: 1.1213x; 1.0211x over previous
#include <cuda_runtime.h>
#include <cuda_fp16.h>
#include <math.h>
#include <stddef.h>
#include <stdint.h>

// ---------------- problem constants ----------------
#define TOKS   8192
#define CDIM   768
#define HID    384
#define NHEAD  12
#define HDIM   64
#define SEQ    1024
#define QKVC   2304
#define NBH    96

// ---------------- scratch ---------------------------
__device__ __half   g_h16[(size_t)TOKS * CDIM];
__device__ float    g_q[(size_t)TOKS * CDIM];
__device__ uint32_t g_khi[(size_t)TOKS * (CDIM / 2)];
__device__ uint32_t g_klo[(size_t)TOKS * (CDIM / 2)];
__device__ uint32_t g_v16[(size_t)TOKS * (CDIM / 2)];
__device__ __half   g_att16[(size_t)TOKS * CDIM];
__device__ float    g_x1[(size_t)TOKS * CDIM];
__device__ __half   g_fc1h[(size_t)TOKS * HID];
__device__ __half   g_wqkv_h[(size_t)QKVC * CDIM];
__device__ __half   g_wproj_h[(size_t)CDIM * CDIM];
__device__ __half   g_wfc1_h[(size_t)HID * CDIM];
__device__ __half   g_wfc2_h[(size_t)CDIM * HID];

typedef unsigned long long u64;

// ---------------- helpers -----------------------
__device__ __forceinline__ uint32_t smem_u32(const void* p) {
    uint32_t a;
    asm("{ .reg .u64 t; cvta.to.shared.u64 t, %1; cvt.u32.u64 %0, t; }" : "=r"(a) : "l"(p));
    return a;
}
__device__ __forceinline__ void cp_async16(uint32_t dst, const void* src) {
    asm volatile("cp.async.cg.shared.global [%0], [%1], 16;" :: "r"(dst), "l"(src));
}
#define CP_COMMIT() asm volatile("cp.async.commit_group;" ::: "memory")

__device__ __forceinline__ void ldsm_x4(uint32_t addr, uint32_t &r0, uint32_t &r1,
                                        uint32_t &r2, uint32_t &r3) {
    asm volatile("ldmatrix.sync.aligned.m8n8.x4.shared.b16 {%0,%1,%2,%3}, [%4];"
                 : "=r"(r0), "=r"(r1), "=r"(r2), "=r"(r3) : "r"(addr));
}
__device__ __forceinline__ void ldsm_x4_t(uint32_t addr, uint32_t &r0, uint32_t &r1,
                                          uint32_t &r2, uint32_t &r3) {
    asm volatile("ldmatrix.sync.aligned.m8n8.x4.trans.shared.b16 {%0,%1,%2,%3}, [%4];"
                 : "=r"(r0), "=r"(r1), "=r"(r2), "=r"(r3) : "r"(addr));
}

__device__ __forceinline__ void mma_fp16(float* d, const uint32_t* a, const uint32_t* b) {
    asm volatile(
        "mma.sync.aligned.m16n8k16.row.col.f32.f16.f16.f32 "
        "{%0,%1,%2,%3}, {%4,%5,%6,%7}, {%8,%9}, {%0,%1,%2,%3};"
        : "+f"(d[0]), "+f"(d[1]), "+f"(d[2]), "+f"(d[3])
        : "r"(a[0]), "r"(a[1]), "r"(a[2]), "r"(a[3]), "r"(b[0]), "r"(b[1]));
}
__device__ __forceinline__ void mma_bf16(float* d, const uint32_t* a, const uint32_t* b) {
    asm volatile(
        "mma.sync.aligned.m16n8k16.row.col.f32.bf16.bf16.f32 "
        "{%0,%1,%2,%3}, {%4,%5,%6,%7}, {%8,%9}, {%0,%1,%2,%3};"
        : "+f"(d[0]), "+f"(d[1]), "+f"(d[2]), "+f"(d[3])
        : "r"(a[0]), "r"(a[1]), "r"(a[2]), "r"(a[3]), "r"(b[0]), "r"(b[1]));
}

__device__ __forceinline__ uint32_t pack_bf16x2(float lo_e, float hi_e) {
    uint32_t r;
    asm("cvt.rn.bf16x2.f32 %0, %1, %2;" : "=r"(r) : "f"(hi_e), "f"(lo_e));
    return r;
}
__device__ __forceinline__ uint32_t pack_half2(float lo_e, float hi_e) {
    uint32_t r;
    asm("cvt.rn.f16x2.f32 %0, %1, %2;" : "=r"(r) : "f"(hi_e), "f"(lo_e));
    return r;
}
__device__ __forceinline__ void split_bf16(float x, float y, uint32_t &hp, uint32_t &lp) {
    hp = pack_bf16x2(x, y);
    float hx = __uint_as_float(hp << 16);
    float hy = __uint_as_float(hp & 0xffff0000u);
    lp = pack_bf16x2(x - hx, y - hy);
}
__device__ __forceinline__ float ex2f(float x) {
    float y;
    asm("ex2.approx.f32 %0, %1;" : "=f"(y) : "f"(x));
    return y;
}

// ---------------- fused weight transpose+convert (all 4 weights) ----------
__global__ void transpose_all(const float* __restrict__ wqkv,
                              const float* __restrict__ wproj,
                              const float* __restrict__ wfc1,
                              const float* __restrict__ wfc2,
                              __half* __restrict__ oqkv, __half* __restrict__ oproj,
                              __half* __restrict__ ofc1, __half* __restrict__ ofc2) {
    const float* in; __half* out; int K, N;
    switch (blockIdx.z) {
        case 0:  in = wqkv;  out = oqkv;  K = CDIM; N = QKVC; break;
        case 1:  in = wproj; out = oproj; K = CDIM; N = CDIM; break;
        case 2:  in = wfc1;  out = ofc1;  K = CDIM; N = HID;  break;
        default: in = wfc2;  out = ofc2;  K = HID;  N = CDIM; break;
    }
    int bn = blockIdx.x << 5, bk = blockIdx.y << 5;
    if (bn >= N || bk >= K) return;
    __shared__ float t[32][33];
    int tx = threadIdx.x, ty = threadIdx.y;
#pragma unroll
    for (int i = 0; i < 4; i++)
        t[ty + i * 8][tx] = in[(size_t)(bk + ty + i * 8) * N + bn + tx];
    __syncthreads();
#pragma unroll
    for (int i = 0; i < 4; i++)
        out[(size_t)(bn + ty + i * 8) * K + bk + tx] = __float2half_rn(t[tx][ty + i * 8]);
}

// ---------------- LayerNorm (fp32 in -> fp16 out) -------------------------
__global__ void ln_kernel(const float* __restrict__ x, const float* __restrict__ w,
                          const float* __restrict__ b, __half* __restrict__ out) {
    int row = blockIdx.x;
    const float* xr = x + (size_t)row * CDIM;
    __half* orow = out + (size_t)row * CDIM;
    int t = threadIdx.x;
    float v0 = xr[t], v1 = xr[t + 256], v2 = xr[t + 512];
    float s = v0 + v1 + v2;
    float q = v0 * v0 + v1 * v1 + v2 * v2;
#pragma unroll
    for (int o = 16; o; o >>= 1) {
        s += __shfl_xor_sync(0xffffffffu, s, o);
        q += __shfl_xor_sync(0xffffffffu, q, o);
    }
    __shared__ float rs[8], rq[8];
    if ((t & 31) == 0) { rs[t >> 5] = s; rq[t >> 5] = q; }
    __syncthreads();
    if (t < 32) {
        float us = (t < 8) ? rs[t] : 0.f;
        float uq = (t < 8) ? rq[t] : 0.f;
#pragma unroll
        for (int o = 4; o; o >>= 1) {
            us += __shfl_xor_sync(0xffffffffu, us, o);
            uq += __shfl_xor_sync(0xffffffffu, uq, o);
        }
        if (t == 0) { rs[0] = us; rq[0] = uq; }
    }
    __syncthreads();
    float mu  = rs[0] * (1.f / CDIM);
    float var = rq[0] * (1.f / CDIM) - mu * mu;
    float inv = rsqrtf(var + 1e-5f);
    orow[t]       = __float2half_rn((v0 - mu) * inv * w[t]       + b[t]);
    orow[t + 256] = __float2half_rn((v1 - mu) * inv * w[t + 256] + b[t + 256]);
    orow[t + 512] = __float2half_rn((v2 - mu) * inv * w[t + 512] + b[t + 512]);
}

// ---------------- fp16 GEMM, BK=64, ldmatrix + qkv-split epilogue ---------
#define GSTG 32768u
__global__ void __launch_bounds__(256, 2)
gemm_fp16(const __half* __restrict__ A, const __half* __restrict__ Bt,
          float* __restrict__ C, __half* __restrict__ C16, int N, int K,
          const float* __restrict__ bias, const float* __restrict__ resid,
          int gelu_flag, int qkv_mode,
          float* __restrict__ Cq, uint32_t* __restrict__ Khi,
          uint32_t* __restrict__ Klo, uint32_t* __restrict__ V16) {
    extern __shared__ char smem[];
    const uint32_t sb = smem_u32(smem);
    const int tid = threadIdx.x;
    const int wid = tid >> 5, lane = tid & 31;
    const int warp_m = wid & 1, warp_n = wid >> 1;
    const int cl = lane & 3;
    const int g  = lane >> 2;
    const int bn = blockIdx.x << 7, bm = blockIdx.y << 7;
    const int nBK = K >> 6;

    float d[4][4][4];
#pragma unroll
    for (int i = 0; i < 4; i++)
#pragma unroll
        for (int j = 0; j < 4; j++)
#pragma unroll
            for (int e = 0; e < 4; e++) d[i][j][e] = 0.f;

#define LOADT(k0, buf)                                                          \
    {                                                                           \
        uint32_t base = sb + ((buf) ? GSTG : 0u);                               \
        _Pragma("unroll")                                                       \
        for (int i = 0; i < 4; i++) {                                           \
            int id = tid + (i << 8);                                            \
            int row = id >> 3, kh = id & 7;                                     \
            uint32_t dst = base + (uint32_t)(row << 7)                          \
                         + (uint32_t)((kh ^ (row & 7)) << 4);                   \
            cp_async16(dst, A + (size_t)(bm + row) * K + (k0) + (kh << 3));     \
            cp_async16(dst + 16384u,                                            \
                       Bt + (size_t)(bn + row) * K + (k0) + (kh << 3));         \
        }                                                                       \
        CP_COMMIT();                                                            \
    }

    LOADT(0, 0);
    if (nBK > 1) LOADT(64, 1);

    const int ar  = (lane & 7) + (((lane >> 3) & 1) << 3);
    const int khp = lane >> 4;
    const int rowa = warp_m * 64 + ar;
    const int rowb = warp_n * 32 + ar;
    const uint32_t sw = (uint32_t)(ar & 7);

    for (int c = 0; c < nBK; c++) {
        int buf = c & 1;
        if (c == nBK - 1) asm volatile("cp.async.wait_group 0;" ::: "memory");
        else              asm volatile("cp.async.wait_group 1;" ::: "memory");
        __syncthreads();

        const uint32_t Sb = sb + (buf ? GSTG : 0u);
        const uint32_t Ab = Sb + (uint32_t)(rowa << 7);
        const uint32_t Bb = Sb + 16384u + (uint32_t)(rowb << 7);

#pragma unroll
        for (int ks = 0; ks < 4; ks++) {
            uint32_t kc = (uint32_t)((((ks << 1) + khp) ^ sw) << 4);
            uint32_t av[4][4], bv[4][2];
#pragma unroll
            for (int mi = 0; mi < 4; mi++)
                ldsm_x4(Ab + (uint32_t)(mi << 11) + kc,
                        av[mi][0], av[mi][1], av[mi][2], av[mi][3]);
#pragma unroll
            for (int j2 = 0; j2 < 2; j2++)
                ldsm_x4(Bb + (uint32_t)(j2 << 11) + kc,
                        bv[j2 * 2][0], bv[j2 * 2 + 1][0],
                        bv[j2 * 2][1], bv[j2 * 2 + 1][1]);
#pragma unroll
            for (int i = 0; i < 4; i++)
#pragma unroll
                for (int j = 0; j < 4; j++) mma_fp16(d[i][j], av[i], bv[j]);
        }
        __syncthreads();
        if (c + 2 < nBK) LOADT((c + 2) << 6, buf);
    }

    const int m0w = bm + warp_m * 64 + g;
    const int n0w = bn + warp_n * 32 + cl * 2;
#pragma unroll
    for (int i = 0; i < 4; i++) {
#pragma unroll
        for (int h = 0; h < 2; h++) {
            int row = m0w + i * 16 + h * 8;
            const float* Rrow = resid ? resid + (size_t)row * N : (const float*)0;
#pragma unroll
            for (int j = 0; j < 4; j++) {
                int col = n0w + j * 8;
                float v0 = d[i][j][h * 2 + 0];
                float v1 = d[i][j][h * 2 + 1];
                if (bias) { v0 += bias[col]; v1 += bias[col + 1]; }
                if (gelu_flag) {
                    v0 = 0.5f * v0 * (1.f + erff(v0 * 0.70710678118654752f));
                    v1 = 0.5f * v1 * (1.f + erff(v1 * 0.70710678118654752f));
                }
                if (Rrow) { v0 += Rrow[col]; v1 += Rrow[col + 1]; }
                if (qkv_mode) {
                    if (bn < CDIM) {
                        *(float2*)&Cq[(size_t)row * CDIM + col] = make_float2(v0, v1);
                    } else if (bn < 2 * CDIM) {
                        uint32_t hp, lp;
                        split_bf16(v0, v1, hp, lp);
                        size_t idx = (size_t)row * (CDIM / 2) + ((col - CDIM) >> 1);
                        Khi[idx] = hp;
                        Klo[idx] = lp;
                    } else {
                        V16[(size_t)row * (CDIM / 2) + ((col - 2 * CDIM) >> 1)] =
                            pack_half2(v0, v1);
                    }
                } else if (C16) {
                    *(uint32_t*)&C16[(size_t)row * N + col] = pack_half2(v0, v1);
                } else {
                    *(float2*)&C[(size_t)row * N + col] = make_float2(v0, v1);
                }
            }
        }
    }
#undef LOADT
}
#define GEMM_SMEM (2 * 32768)

// ---------------- flash attention: register-direct P, log2-domain softmax -
// P never touches smem: the S-MMA D-fragment layout IS the PV A-fragment
// layout (a = {pack(s[2ks][0,1]), pack(s[2ks][2,3]), pack(s[2ks+1][0,1]),
// pack(s[2ks+1][2,3])}). Softmax in log2 domain (8*log2e folded into Q).
#define QS 36
#define QSB 144u
#define KVSTG 8192u
#define QSCALE 11.5416211521f   /* 8 * log2(e) */

__global__ void __launch_bounds__(256, 2)
flash_mma(const float* __restrict__ q, const uint32_t* __restrict__ khi,
          const uint32_t* __restrict__ klo, const uint32_t* __restrict__ v16,
          __half* __restrict__ att16) {
    extern __shared__ char smc[];
    uint32_t* Qhb = (uint32_t*)smc;            // [128][QS]
    uint32_t* Qlb = Qhb + 128 * QS;            // [128][QS]
    char* Kh0 = (char*)(Qlb + 128 * QS);       // 2 x 8192
    char* Kl0 = Kh0 + 2 * KVSTG;               // 2 x 8192
    char* Vv0 = Kl0 + 2 * KVSTG;               // 2 x 8192

    const int tid = threadIdx.x;
    const int wid = tid >> 5, lane = tid & 31;
    const int r = lane >> 2, cl = lane & 3;
    const int qb = blockIdx.x << 7;
    const int bh = blockIdx.y;
    const int b = bh / NHEAD, h = bh % NHEAD;

    const uint32_t kh_sb = smem_u32(Kh0);
    const uint32_t kl_sb = smem_u32(Kl0);
    const uint32_t vv_sb = smem_u32(Vv0);

    const uint32_t* kh_g = khi + (size_t)(b * SEQ) * (CDIM / 2) + h * (HDIM / 2);
    const uint32_t* kl_g = klo + (size_t)(b * SEQ) * (CDIM / 2) + h * (HDIM / 2);
    const uint32_t* vv_g = v16 + (size_t)(b * SEQ) * (CDIM / 2) + h * (HDIM / 2);

    const int lrow = tid >> 2;
    const int lc2 = (tid & 3) << 1;

#define LOADKV(t, stg)                                                          \
    {                                                                           \
        size_t gro = (size_t)(((t) << 6) + lrow) * (CDIM / 2);                  \
        uint32_t so = (uint32_t)(stg) * KVSTG + (uint32_t)(lrow << 7);          \
        _Pragma("unroll")                                                       \
        for (int e = 0; e < 2; e++) {                                           \
            int ch = lc2 + e;                                                   \
            uint32_t sws = so + (uint32_t)((ch ^ (lrow & 7)) << 4);             \
            cp_async16(kh_sb + sws, kh_g + gro + (ch << 2));                    \
            cp_async16(kl_sb + sws, kl_g + gro + (ch << 2));                    \
            cp_async16(vv_sb + sws, vv_g + gro + (ch << 2));                    \
        }                                                                       \
        CP_COMMIT();                                                            \
    }

    LOADKV(0, 0);

    // ---- load Q (fp32, scale folded: 8*log2e), split bf16 hi/lo pairs ----
    {
        int row = tid >> 1;
        const float* src = q + (size_t)(b * SEQ + qb + row) * CDIM + h * HDIM;
#pragma unroll
        for (int e = 0; e < 8; e++) {
            int c4 = ((tid & 1) << 3) + e;
            float2 v = *(const float2*)(src + (c4 << 1));
            v.x *= QSCALE; v.y *= QSCALE;
            uint32_t hp, lp;
            split_bf16(v.x, v.y, hp, lp);
            Qhb[row * QS + c4] = hp;
            Qlb[row * QS + c4] = lp;
        }
#pragma unroll
        for (int e = 0; e < 8; e++) {
            int c4 = 16 + ((tid & 1) << 3) + e;
            float2 v = *(const float2*)(src + (c4 << 1));
            v.x *= QSCALE; v.y *= QSCALE;
            uint32_t hp, lp;
            split_bf16(v.x, v.y, hp, lp);
            Qhb[row * QS + c4] = hp;
            Qlb[row * QS + c4] = lp;
        }
    }

    float mi0 = -3.4e38f, mi1 = -3.4e38f, li0 = 0.f, li1 = 0.f;
    float o[8][4];
#pragma unroll
    for (int j = 0; j < 8; j++)
#pragma unroll
        for (int e = 0; e < 4; e++) o[j][e] = 0.f;

    const int m0 = wid << 4;
    const int fr8 = (lane & 7) + (((lane >> 3) & 1) << 3);
    const uint32_t khf16 = (uint32_t)(lane >> 4) << 4;
    const uint32_t qh_b = smem_u32(Qhb) + (uint32_t)(m0 + fr8) * QSB + khf16;
    const uint32_t ql_b = smem_u32(Qlb) + (uint32_t)(m0 + fr8) * QSB + khf16;
    const uint32_t sw7 = (uint32_t)(lane & 7);
    const int khpi = lane >> 4;
    const uint32_t kfr_off = (uint32_t)(fr8 << 7);
    const uint32_t vrow_off = (uint32_t)(((lane >> 4) << 3) + (lane & 7)) << 7;
    const int vch = (lane >> 3) & 1;

    for (int t = 0; t < 16; t++) {
        int stg = t & 1;
        asm volatile("cp.async.wait_group 0;" ::: "memory");
        __syncthreads();
        if (t + 1 < 16) LOADKV(t + 1, stg ^ 1);

        const uint32_t khb = kh_sb + (uint32_t)stg * KVSTG + kfr_off;
        const uint32_t klb = kl_sb + (uint32_t)stg * KVSTG + kfr_off;
        const uint32_t vvb = vv_sb + (uint32_t)stg * KVSTG + vrow_off;

        // ---- S = Q K^T (bf16x3, m16n8k16), logits in log2 domain ----
        float s[8][4];
#pragma unroll
        for (int j = 0; j < 8; j++)
#pragma unroll
            for (int e = 0; e < 4; e++) s[j][e] = 0.f;

#pragma unroll
        for (int ks = 0; ks < 4; ks++) {
            uint32_t ko = (uint32_t)(ks << 5);
            uint32_t kc = (uint32_t)((((ks << 1) + khpi) ^ sw7) << 4);
            uint32_t ah[4], al[4];
            ldsm_x4(qh_b + ko, ah[0], ah[1], ah[2], ah[3]);
            ldsm_x4(ql_b + ko, al[0], al[1], al[2], al[3]);
#pragma unroll
            for (int jp = 0; jp < 4; jp++) {
                uint32_t jo = (uint32_t)(jp << 11);
                uint32_t bh2[2][2], bl2[2][2];
                ldsm_x4(khb + jo + kc, bh2[0][0], bh2[1][0], bh2[0][1], bh2[1][1]);
                ldsm_x4(klb + jo + kc, bl2[0][0], bl2[1][0], bl2[0][1], bl2[1][1]);
#pragma unroll
                for (int jj = 0; jj < 2; jj++) {
                    int j = jp * 2 + jj;
                    mma_bf16(s[j], ah, bh2[jj]);
                    mma_bf16(s[j], al, bh2[jj]);
                    mma_bf16(s[j], ah, bl2[jj]);
                }
            }
        }

        // ---- online softmax, log2 domain (rows m0+r, m0+r+8) ----
        float mx0 = s[0][0], mx1 = s[0][2];
#pragma unroll
        for (int j = 0; j < 8; j++) {
            mx0 = fmaxf(mx0, fmaxf(s[j][0], s[j][1]));
            mx1 = fmaxf(mx1, fmaxf(s[j][2], s[j][3]));
        }
        mx0 = fmaxf(mx0, __shfl_xor_sync(0xffffffffu, mx0, 1));
        mx0 = fmaxf(mx0, __shfl_xor_sync(0xffffffffu, mx0, 2));
        mx1 = fmaxf(mx1, __shfl_xor_sync(0xffffffffu, mx1, 1));
        mx1 = fmaxf(mx1, __shfl_xor_sync(0xffffffffu, mx1, 2));
        float mn0 = fmaxf(mi0, mx0), mn1 = fmaxf(mi1, mx1);
        float sc0 = ex2f(mi0 - mn0), sc1 = ex2f(mi1 - mn1);
        mi0 = mn0; mi1 = mn1;
        float sum0 = 0.f, sum1 = 0.f;
#pragma unroll
        for (int j = 0; j < 8; j++) {
            s[j][0] = ex2f(s[j][0] - mn0);
            s[j][1] = ex2f(s[j][1] - mn0);
            s[j][2] = ex2f(s[j][2] - mn1);
            s[j][3] = ex2f(s[j][3] - mn1);
            sum0 += s[j][0] + s[j][1];
            sum1 += s[j][2] + s[j][3];
        }
        sum0 += __shfl_xor_sync(0xffffffffu, sum0, 1);
        sum0 += __shfl_xor_sync(0xffffffffu, sum0, 2);
        sum1 += __shfl_xor_sync(0xffffffffu, sum1, 1);
        sum1 += __shfl_xor_sync(0xffffffffu, sum1, 2);
        li0 = li0 * sc0 + sum0;
        li1 = li1 * sc1 + sum1;
#pragma unroll
        for (int j = 0; j < 8; j++) {
            o[j][0] *= sc0; o[j][1] *= sc0;
            o[j][2] *= sc1; o[j][3] *= sc1;
        }

        // ---- O += P @ V: P A-frags built DIRECTLY from S fragments ----
#pragma unroll
        for (int ks = 0; ks < 4; ks++) {
            uint32_t a[4];
            a[0] = pack_half2(s[2 * ks][0],     s[2 * ks][1]);
            a[1] = pack_half2(s[2 * ks][2],     s[2 * ks][3]);
            a[2] = pack_half2(s[2 * ks + 1][0], s[2 * ks + 1][1]);
            a[3] = pack_half2(s[2 * ks + 1][2], s[2 * ks + 1][3]);
            uint32_t vrow = vvb + (uint32_t)(ks << 11);
#pragma unroll
            for (int jp = 0; jp < 4; jp++) {
                uint32_t vc = (uint32_t)((((jp << 1) + vch) ^ sw7) << 4);
                uint32_t b2[2][2];
                ldsm_x4_t(vrow + vc, b2[0][0], b2[1][0], b2[0][1], b2[1][1]);
                mma_fp16(o[jp * 2 + 0], a, b2[0]);
                mma_fp16(o[jp * 2 + 1], a, b2[1]);
            }
        }
        __syncthreads();
    }

    // ---- epilogue: O / l -> att16 in [B,N,C] ----
    {
        float inv0 = 1.f / li0, inv1 = 1.f / li1;
        __half* o0 = att16 + ((size_t)(b * SEQ + qb + m0 + r)) * CDIM + h * HDIM;
        __half* o1 = o0 + 8 * CDIM;
#pragma unroll
        for (int j = 0; j < 8; j++) {
            int col = (j << 3) + (cl << 1);
            *(uint32_t*)&o0[col] = pack_half2(o[j][0] * inv0, o[j][1] * inv0);
            *(uint32_t*)&o1[col] = pack_half2(o[j][2] * inv1, o[j][3] * inv1);
        }
    }
#undef LOADKV
}
#define FLASH_SMEM (2 * 128 * QS * 4 + 3 * 2 * KVSTG)

// ---------------- launch --------------------------------------------------
extern "C" void kernel_launch(void* const* d_in, const int* in_sizes, int n_in,
                              void* d_out, int out_size) {
    const float* x     = (const float*)d_in[0];
    const float* ln1w  = (const float*)d_in[1];
    const float* ln1b  = (const float*)d_in[2];
    const float* ln2w  = (const float*)d_in[3];
    const float* ln2b  = (const float*)d_in[4];
    const float* wqkv  = (const float*)d_in[5];
    const float* wproj = (const float*)d_in[6];
    const float* wfc1  = (const float*)d_in[7];
    const float* bfc1  = (const float*)d_in[8];
    const float* wfc2  = (const float*)d_in[9];
    const float* bfc2  = (const float*)d_in[10];
    float* out = (float*)d_out;

    __half *p_h16, *p_att16, *p_fc1h, *p_wqkv_h, *p_wproj_h, *p_wfc1_h, *p_wfc2_h;
    float *p_q, *p_x1;
    uint32_t *p_khi, *p_klo, *p_v16;
    cudaGetSymbolAddress((void**)&p_h16, g_h16);
    cudaGetSymbolAddress((void**)&p_q, g_q);
    cudaGetSymbolAddress((void**)&p_khi, g_khi);
    cudaGetSymbolAddress((void**)&p_klo, g_klo);
    cudaGetSymbolAddress((void**)&p_v16, g_v16);
    cudaGetSymbolAddress((void**)&p_att16, g_att16);
    cudaGetSymbolAddress((void**)&p_x1, g_x1);
    cudaGetSymbolAddress((void**)&p_fc1h, g_fc1h);
    cudaGetSymbolAddress((void**)&p_wqkv_h, g_wqkv_h);
    cudaGetSymbolAddress((void**)&p_wproj_h, g_wproj_h);
    cudaGetSymbolAddress((void**)&p_wfc1_h, g_wfc1_h);
    cudaGetSymbolAddress((void**)&p_wfc2_h, g_wfc2_h);

    cudaFuncSetAttribute(flash_mma, cudaFuncAttributeMaxDynamicSharedMemorySize,
                         FLASH_SMEM);
    cudaFuncSetAttribute(gemm_fp16, cudaFuncAttributeMaxDynamicSharedMemorySize,
                         GEMM_SMEM);

    transpose_all<<<dim3(QKVC / 32, CDIM / 32, 4), dim3(32, 8)>>>(
        wqkv, wproj, wfc1, wfc2, p_wqkv_h, p_wproj_h, p_wfc1_h, p_wfc2_h);

    // 1) h = LN1(x)
    ln_kernel<<<TOKS, 256>>>(x, ln1w, ln1b, p_h16);
    // 2) qkv GEMM with split epilogue: q fp32, k bf16 hi/lo, v fp16
    gemm_fp16<<<dim3(QKVC / 128, TOKS / 128), 256, GEMM_SMEM>>>(
        p_h16, p_wqkv_h, nullptr, nullptr, QKVC, CDIM, nullptr, nullptr, 0,
        1, p_q, p_khi, p_klo, p_v16);
    // 3-5) fused attention
    flash_mma<<<dim3(SEQ / 128, NBH), 256, FLASH_SMEM>>>(
        p_q, p_khi, p_klo, p_v16, p_att16);
    // 6) x1 = x + att @ w_proj
    gemm_fp16<<<dim3(CDIM / 128, TOKS / 128), 256, GEMM_SMEM>>>(
        p_att16, p_wproj_h, p_x1, nullptr, CDIM, CDIM, nullptr, x, 0,
        0, nullptr, nullptr, nullptr, nullptr);
    // 7) h = LN2(x1)
    ln_kernel<<<TOKS, 256>>>(p_x1, ln2w, ln2b, p_h16);
    // 8) fc1 = gelu(h @ w_fc1 + b_fc1)
    gemm_fp16<<<dim3(HID / 128, TOKS / 128), 256, GEMM_SMEM>>>(
        p_h16, p_wfc1_h, nullptr, p_fc1h, HID, CDIM, bfc1, nullptr, 1,
        0, nullptr, nullptr, nullptr, nullptr);
    // 9) out = x1 + fc1 @ w_fc2 + b_fc2
    gemm_fp16<<<dim3(CDIM / 128, TOKS / 128), 256, GEMM_SMEM>>>(
        p_fc1h, p_wfc2_h, out, nullptr, CDIM, HID, bfc2, p_x1, 0,
        0, nullptr, nullptr, nullptr, nullptr);
}